// round 1
// baseline (speedup 1.0000x reference)
#include <cuda_runtime.h>
#include <math.h>

// Shapes (fixed by the problem)
#define Bn   16
#define Hh   64
#define Ww   64
#define C1   16
#define C2   16
#define HIDc 128
#define OC4  272          // C2 * (C2+1) = 16*17
#define NPIX (Bn*Hh*Ww)   // 65536

// ---------------- scratch (device globals: allocation-free) ----------------
__device__ float g_x1t[NPIX * C1];     //  4 MB  NHWC x[:, :16]
__device__ float g_x2t[NPIX * C2];     //  4 MB  NHWC x[:, 16:]
__device__ float g_h0 [NPIX * HIDc];   // 33.5 MB
__device__ float g_h1 [NPIX * HIDc];   // 33.5 MB
__device__ float g_o  [NPIX * OC4];    // 71.3 MB

// ---------------------------------------------------------------------------
// prep: NCHW -> NHWC split, x1 passthrough copy to out, zero log_det
// ---------------------------------------------------------------------------
__global__ void prep_kernel(const float* __restrict__ x,
                            float* __restrict__ out)   // out: NCHW (B,32,H,W) then logdet[B]
{
    int idx = blockIdx.x * blockDim.x + threadIdx.x;
    if (idx < Bn) out[(size_t)Bn * 32 * Hh * Ww + idx] = 0.0f;   // zero log_det
    if (idx >= Bn * 32 * Hh * Ww) return;
    int b = idx >> 17;              // 32*4096 = 131072
    int c = (idx >> 12) & 31;
    int p = idx & 4095;             // y*64 + x
    float v = x[idx];
    int pix = (b << 12) + p;
    if (c < C1) {
        out[idx] = v;                       // x1 passthrough
        g_x1t[pix * C1 + c] = v;
    } else {
        g_x2t[pix * C2 + (c - C1)] = v;
    }
}

// ---------------------------------------------------------------------------
// Generic 3x3 SAME conv, NHWC, fused bias (+optional ELU).
// Block: 256 threads = 16 pixgrp (4 px each -> full 64-wide row) x 16 ocgrp (8 oc each).
// Grid: (B*H, ceil(OC/128)).  Inputs chunked by 8 input channels through SMEM.
// ---------------------------------------------------------------------------
template<int IC>
__global__ __launch_bounds__(256)
void conv3x3_kernel(const float* __restrict__ in,    // [B,H,W,IC]
                    const float* __restrict__ wgt,   // [OC,IC,3,3]
                    const float* __restrict__ bias,  // [OC]
                    float* __restrict__ out,         // [B,H,W,OC_total]
                    int OC_total, int do_elu)
{
    __shared__ float s_in[3][66][8];     // [dy][x+1][ic]
    __shared__ float s_w [9][8][128];    // [tap][ic][oc within tile]

    const int tid  = threadIdx.x;
    const int ocg  = tid & 15;           // 0..15, 8 oc each
    const int pxg  = tid >> 4;           // 0..15, 4 px each
    const int x0   = pxg * 4;
    const int row  = blockIdx.x;         // b*H + y
    const int b    = row >> 6;
    const int y    = row & 63;
    const int oc_base = blockIdx.y * 128;

    float acc[4][8];
    #pragma unroll
    for (int p = 0; p < 4; p++)
        #pragma unroll
        for (int j = 0; j < 8; j++) acc[p][j] = 0.0f;

    for (int c0 = 0; c0 < IC; c0 += 8) {
        __syncthreads();
        // --- stage input row-strip (3 rows x 66 cols x 8 ic) ---
        for (int t = tid; t < 3 * 66 * 8; t += 256) {
            int ic = t & 7;
            int xx = (t >> 3) % 66;
            int dy = t / (66 * 8);
            int gy = y + dy - 1;
            int gx = xx - 1;
            float v = 0.0f;
            if (gy >= 0 && gy < Hh && gx >= 0 && gx < Ww)
                v = in[(((size_t)(b * Hh + gy) * Ww + gx)) * IC + c0 + ic];
            s_in[dy][xx][ic] = v;
        }
        // --- stage weights (9 taps x 8 ic x 128 oc) ---
        for (int t = tid; t < 9 * 8 * 128; t += 256) {
            int oc  = t & 127;
            int ic  = (t >> 7) & 7;
            int tap = t >> 10;
            float v = 0.0f;
            int oc_g = oc_base + oc;
            if (oc_g < OC_total)
                v = wgt[((size_t)oc_g * IC + (c0 + ic)) * 9 + tap];
            s_w[tap][ic][oc] = v;
        }
        __syncthreads();

        // --- compute ---
        #pragma unroll
        for (int tap = 0; tap < 9; tap++) {
            const int dy = tap / 3, dx = tap % 3;
            #pragma unroll
            for (int ic = 0; ic < 8; ic++) {
                float wv[8];
                *(float4*)&wv[0] = *(const float4*)&s_w[tap][ic][ocg * 8];
                *(float4*)&wv[4] = *(const float4*)&s_w[tap][ic][ocg * 8 + 4];
                #pragma unroll
                for (int p = 0; p < 4; p++) {
                    float iv = s_in[dy][x0 + p + dx][ic];
                    #pragma unroll
                    for (int j = 0; j < 8; j++) acc[p][j] += iv * wv[j];
                }
            }
        }
    }

    // --- epilogue: bias + ELU + store (NHWC) ---
    const int oc0 = oc_base + ocg * 8;
    if (oc0 < OC_total) {
        float bv[8];
        #pragma unroll
        for (int j = 0; j < 8; j++) bv[j] = bias[oc0 + j];
        #pragma unroll
        for (int p = 0; p < 4; p++) {
            float v[8];
            #pragma unroll
            for (int j = 0; j < 8; j++) {
                float t = acc[p][j] + bv[j];
                v[j] = do_elu ? (t > 0.0f ? t : expm1f(t)) : t;
            }
            float* op = out + ((size_t)row * Ww + x0 + p) * OC_total + oc0;
            *(float4*)&op[0] = *(float4*)&v[0];
            *(float4*)&op[4] = *(float4*)&v[4];
        }
    }
}

// ---------------------------------------------------------------------------
// expm kernel: per pixel, A = rescale*tanh(scale*W + shift_p) + reshift (16x16),
// acc = sum_{k=0..18} A^k/k!, y2 = acc @ x2 + shift.  trace(A) -> log_det.
// Block: 256 thr = 8 warps = 16 pixels (half-warp/pixel, lane = matrix row).
// ---------------------------------------------------------------------------
__global__ __launch_bounds__(256)
void expm_kernel(const float* __restrict__ o,        // [NPIX, 272]
                 const float* __restrict__ scale, const float* __restrict__ shift_p,
                 const float* __restrict__ rescale, const float* __restrict__ reshift,
                 float* __restrict__ out)             // NCHW (B,32,H,W) + logdet[B]
{
    __shared__ float sA[16][16][16];   // [pixInBlk][m][j]
    __shared__ float sX[16][16];       // x2 vectors
    __shared__ float sY[16][17];       // staged outputs (padded)
    __shared__ float sTr[8];

    const int tid   = threadIdx.x;
    const int lane  = tid & 31;
    const int warp  = tid >> 5;
    const int half  = lane >> 4;
    const int r     = lane & 15;
    const int pixB  = warp * 2 + half;

    const int pix_base = blockIdx.x * 16;
    const int b  = pix_base >> 12;
    const int p  = pix_base & 4095;
    const int y  = p >> 6;
    const int x0 = p & 63;
    const int pix = pix_base + pixB;

    const float sc = scale[0], sp = shift_p[0], rs = rescale[0], rf = reshift[0];
    const float* op = o + (size_t)pix * OC4;

    // A row r (tanh transform) + trace contribution
    float arow[16];
    #pragma unroll
    for (int j = 0; j < 16; j++) {
        float v = op[(j + 1) * 16 + r];
        arow[j] = rs * tanhf(sc * v + sp) + rf;
    }
    float tr = arow[r];

    #pragma unroll
    for (int j = 0; j < 16; j++) sA[pixB][r][j] = arow[j];
    sX[pixB][r] = g_x2t[(size_t)pix * 16 + r];
    __syncwarp();

    // Taylor: term = A, acc = I + A
    float term[16], acc[16];
    #pragma unroll
    for (int j = 0; j < 16; j++) {
        term[j] = arow[j];
        acc[j]  = arow[j] + (j == r ? 1.0f : 0.0f);
    }

    #pragma unroll 1
    for (int k = 2; k <= 18; k++) {
        float c[16];
        #pragma unroll
        for (int j = 0; j < 16; j++) c[j] = 0.0f;
        #pragma unroll
        for (int m = 0; m < 16; m++) {
            float t = term[m];
            #pragma unroll
            for (int j = 0; j < 16; j++) c[j] += t * sA[pixB][m][j];
        }
        float inv = 1.0f / (float)k;
        #pragma unroll
        for (int j = 0; j < 16; j++) { term[j] = c[j] * inv; acc[j] += term[j]; }
    }

    // matvec + shift
    float y2 = 0.0f;
    #pragma unroll
    for (int j = 0; j < 16; j++) y2 += acc[j] * sX[pixB][j];
    y2 += op[r];                 // shift channel r
    sY[pixB][r] = y2;

    // trace reduce (warp -> block -> one atomic)
    #pragma unroll
    for (int off = 16; off > 0; off >>= 1) tr += __shfl_down_sync(0xffffffffu, tr, off);
    if (lane == 0) sTr[warp] = tr;
    __syncthreads();
    if (tid == 0) {
        float s = 0.0f;
        #pragma unroll
        for (int w2 = 0; w2 < 8; w2++) s += sTr[w2];
        atomicAdd(out + (size_t)Bn * 32 * Hh * Ww + b, s);
    }

    // coalesced NCHW store: channel c = tid/16, pixel = tid%16
    const int c  = tid >> 4;
    const int p2 = tid & 15;
    out[((size_t)(b * 32 + 16 + c)) * (Hh * Ww) + y * Ww + x0 + p2] = sY[p2][c];
}

// ---------------------------------------------------------------------------
extern "C" void kernel_launch(void* const* d_in, const int* in_sizes, int n_in,
                              void* d_out, int out_size)
{
    const float* x       = (const float*)d_in[0];
    const float* scale   = (const float*)d_in[1];
    const float* shift_p = (const float*)d_in[2];
    const float* rescale = (const float*)d_in[3];
    const float* reshift = (const float*)d_in[4];
    const float* w0 = (const float*)d_in[5];
    const float* b0 = (const float*)d_in[6];
    const float* w1 = (const float*)d_in[7];
    const float* b1 = (const float*)d_in[8];
    const float* w2 = (const float*)d_in[9];
    const float* b2 = (const float*)d_in[10];
    const float* w3 = (const float*)d_in[11];
    const float* b3 = (const float*)d_in[12];
    float* out = (float*)d_out;

    float *x1t, *x2t, *h0, *h1, *oB;
    cudaGetSymbolAddress((void**)&x1t, g_x1t);
    cudaGetSymbolAddress((void**)&x2t, g_x2t);
    cudaGetSymbolAddress((void**)&h0,  g_h0);
    cudaGetSymbolAddress((void**)&h1,  g_h1);
    cudaGetSymbolAddress((void**)&oB,  g_o);

    // 1) split / passthrough
    {
        int n = Bn * 32 * Hh * Ww;
        prep_kernel<<<(n + 255) / 256, 256>>>(x, out);
    }
    // 2) conv0: 16 -> 128, ELU
    conv3x3_kernel<C1><<<dim3(Bn * Hh, 1), 256>>>(x1t, w0, b0, h0, HIDc, 1);
    // 3) conv1: 128 -> 128, ELU
    conv3x3_kernel<HIDc><<<dim3(Bn * Hh, 1), 256>>>(h0, w1, b1, h1, HIDc, 1);
    // 4) conv2: 128 -> 128, ELU
    conv3x3_kernel<HIDc><<<dim3(Bn * Hh, 1), 256>>>(h1, w2, b2, h0, HIDc, 1);
    // 5) conv3: 128 -> 272, no activation
    conv3x3_kernel<HIDc><<<dim3(Bn * Hh, 3), 256>>>(h0, w3, b3, oB, OC4, 0);
    // 6) per-pixel matrix exponential + output assembly + log_det
    expm_kernel<<<NPIX / 16, 256>>>(oB, scale, shift_p, rescale, reshift, out);

    (void)in_sizes; (void)n_in; (void)out_size;
}

// round 3
// speedup vs baseline: 4.0944x; 4.0944x over previous
#include <cuda_runtime.h>
#include <cuda_bf16.h>
#include <math.h>
#include <stdint.h>

// Shapes (fixed)
#define Bn   16
#define Hh   64
#define Ww   64
#define C1   16
#define C2   16
#define HIDc 128
#define OC4  272          // C2*(C2+1)
#define NPIX (Bn*Hh*Ww)   // 65536

// ---------------------------------------------------------------------------
__device__ __forceinline__ uint32_t smem_u32(const void* p) {
    uint32_t a;
    asm("{ .reg .u64 t; cvta.to.shared.u64 t, %1; cvt.u32.u64 %0, t; }" : "=r"(a) : "l"(p));
    return a;
}

__device__ __forceinline__ void ldsm_x4(uint32_t (&r)[4], uint32_t addr) {
    asm volatile("ldmatrix.sync.aligned.m8n8.x4.shared.b16 {%0,%1,%2,%3}, [%4];"
        : "=r"(r[0]), "=r"(r[1]), "=r"(r[2]), "=r"(r[3]) : "r"(addr));
}

__device__ __forceinline__ void mma16816(float (&d)[4], const uint32_t (&a)[4],
                                         uint32_t b0, uint32_t b1) {
    asm volatile("mma.sync.aligned.m16n8k16.row.col.f32.bf16.bf16.f32 "
        "{%0,%1,%2,%3}, {%4,%5,%6,%7}, {%8,%9}, {%0,%1,%2,%3};"
        : "+f"(d[0]), "+f"(d[1]), "+f"(d[2]), "+f"(d[3])
        : "r"(a[0]), "r"(a[1]), "r"(a[2]), "r"(a[3]), "r"(b0), "r"(b1));
}

__device__ __forceinline__ float eluf(float t) { return t > 0.0f ? t : expm1f(t); }

// ---------------- scratch (device globals) ----------------
__device__ __nv_bfloat16 g_x1h[NPIX * C1];
__device__ __nv_bfloat16 g_x1l[NPIX * C1];
__device__ float         g_x2t[NPIX * C2];
__device__ __nv_bfloat16 g_a0h[NPIX * HIDc];
__device__ __nv_bfloat16 g_a0l[NPIX * HIDc];
__device__ __nv_bfloat16 g_a1h[NPIX * HIDc];
__device__ __nv_bfloat16 g_a1l[NPIX * HIDc];
__device__ float         g_o  [(size_t)NPIX * OC4];
// pre-tiled weights, plain [tile][tap][128 oc][ICA] bf16, hi/lo
__device__ __nv_bfloat16 g_wb0h[9 * 128 * 16];
__device__ __nv_bfloat16 g_wb0l[9 * 128 * 16];
__device__ __nv_bfloat16 g_wb1h[9 * 128 * 128];
__device__ __nv_bfloat16 g_wb1l[9 * 128 * 128];
__device__ __nv_bfloat16 g_wb2h[9 * 128 * 128];
__device__ __nv_bfloat16 g_wb2l[9 * 128 * 128];
__device__ __nv_bfloat16 g_wb3h[3 * 9 * 128 * 128];
__device__ __nv_bfloat16 g_wb3l[3 * 9 * 128 * 128];

// ---------------------------------------------------------------------------
// prep: NCHW -> NHWC split (x1 as bf16 hi/lo, x2 fp32), passthrough, zero logdet
// ---------------------------------------------------------------------------
__global__ void prep_kernel(const float* __restrict__ x, float* __restrict__ out)
{
    int idx = blockIdx.x * blockDim.x + threadIdx.x;
    if (idx < Bn) out[(size_t)Bn * 32 * Hh * Ww + idx] = 0.0f;
    if (idx >= Bn * 32 * Hh * Ww) return;
    int b = idx >> 17;
    int c = (idx >> 12) & 31;
    int p = idx & 4095;
    float v = x[idx];
    int pix = (b << 12) + p;
    if (c < C1) {
        out[idx] = v;
        __nv_bfloat16 h = __float2bfloat16_rn(v);
        g_x1h[pix * C1 + c] = h;
        g_x1l[pix * C1 + c] = __float2bfloat16_rn(v - __bfloat162float(h));
    } else {
        g_x2t[pix * C2 + (c - C1)] = v;
    }
}

// ---------------------------------------------------------------------------
// wprep: w[OC][ICA][3][3] fp32 -> [tile][tap][128][ICA] bf16 hi/lo (plain)
// ---------------------------------------------------------------------------
__global__ void wprep_kernel(const float* __restrict__ w,
                             __nv_bfloat16* __restrict__ dh,
                             __nv_bfloat16* __restrict__ dl,
                             int OC, int ICA, int total)
{
    int idx = blockIdx.x * blockDim.x + threadIdx.x;
    if (idx >= total) return;
    int k   = idx % ICA;
    int row = (idx / ICA) & 127;
    int tt  = idx / (ICA * 128);
    int tap  = tt % 9;
    int tile = tt / 9;
    int oc = tile * 128 + row;
    float v = (oc < OC) ? w[((size_t)oc * ICA + k) * 9 + tap] : 0.0f;
    __nv_bfloat16 h = __float2bfloat16_rn(v);
    dh[idx] = h;
    dl[idx] = __float2bfloat16_rn(v - __bfloat162float(h));
}

// ---------------------------------------------------------------------------
// Implicit 3x3 conv via mma.sync (bf16 hi/lo, fp32 accum in registers).
// CTA = 128 px x 128 oc, 8 warps (2M x 4N), warp tile 64 px x 32 oc.
// Per tap: stage A(hi/lo) + B(hi/lo) into padded SMEM, then k16-step MMAs.
// ---------------------------------------------------------------------------
template<int ICA>
__global__ __launch_bounds__(256, 1)
void conv_mma_kernel(const __nv_bfloat16* __restrict__ in_hi,
                     const __nv_bfloat16* __restrict__ in_lo,
                     const __nv_bfloat16* __restrict__ wb_hi,
                     const __nv_bfloat16* __restrict__ wb_lo,
                     const float* __restrict__ bias,
                     __nv_bfloat16* __restrict__ out_hi,
                     __nv_bfloat16* __restrict__ out_lo,
                     float* __restrict__ out_f32,
                     int OC_total)
{
    constexpr int PITCH = ICA + 8;       // elements (pad kills ldmatrix conflicts)
    constexpr int PB    = PITCH * 2;     // bytes per row
    constexpr int TILEB = 128 * PB;      // bytes per buffer
    constexpr int VPA   = ICA / 8;       // 16B vectors per row (real data)
    constexpr int KC    = ICA / 16;      // k16 steps per tap

    extern __shared__ char smem[];
    char* pAh = smem;
    char* pAl = pAh + TILEB;
    char* pBh = pAl + TILEB;
    char* pBl = pBh + TILEB;
    const uint32_t sAh = smem_u32(pAh), sAl = sAh + TILEB,
                   sBh = sAl + TILEB,  sBl = sBh + TILEB;

    const int tid  = threadIdx.x;
    const int lane = tid & 31;
    const int warp = tid >> 5;
    const int warpM = warp & 1;     // 0..1 -> 64 px each
    const int warpN = warp >> 1;    // 0..3 -> 32 oc each

    const int pixbase = blockIdx.x * 128;
    const int b  = pixbase >> 12;
    const int y0 = (pixbase & 4095) >> 6;
    const int ocb = blockIdx.y;
    const bool active = (ocb * 128 + warpN * 32) < OC_total;

    float acc[4][4][4];
    #pragma unroll
    for (int mt = 0; mt < 4; mt++)
        #pragma unroll
        for (int nt = 0; nt < 4; nt++)
            #pragma unroll
            for (int q = 0; q < 4; q++) acc[mt][nt][q] = 0.0f;

    // per-lane ldmatrix base offsets (byte offsets within tile, before k0)
    const uint32_t a_base = (uint32_t)(warpM * 64 + (lane & 15)) * PB + (uint32_t)(lane & 16);
    const uint32_t b_base = (uint32_t)(warpN * 32 + (lane & 7) + ((lane & 16) >> 1)) * PB
                          + (uint32_t)((lane & 8) << 1);

    for (int tap = 0; tap < 9; tap++) {
        const int dy = tap / 3 - 1, dx = tap % 3 - 1;
        __syncthreads();
        // --- stage A (hi+lo), boundary zeros ---
        for (int vi = tid; vi < 128 * VPA; vi += 256) {
            int px = vi / VPA;
            int kv = vi % VPA;
            int yy = y0 + (px >> 6) + dy;
            int xx = (px & 63) + dx;
            uint4 vh = make_uint4(0, 0, 0, 0), vl = make_uint4(0, 0, 0, 0);
            if (yy >= 0 && yy < Hh && xx >= 0 && xx < Ww) {
                size_t src = ((size_t)((b << 12) + (yy << 6) + xx)) * ICA + kv * 8;
                vh = *(const uint4*)(in_hi + src);
                vl = *(const uint4*)(in_lo + src);
            }
            *(uint4*)(pAh + px * PB + kv * 16) = vh;
            *(uint4*)(pAl + px * PB + kv * 16) = vl;
        }
        // --- stage B (hi+lo) ---
        {
            const uint4* sh = (const uint4*)(wb_hi + ((size_t)(ocb * 9 + tap)) * 128 * ICA);
            const uint4* sl = (const uint4*)(wb_lo + ((size_t)(ocb * 9 + tap)) * 128 * ICA);
            for (int vi = tid; vi < 128 * VPA; vi += 256) {
                int row = vi / VPA;
                int kv = vi % VPA;
                *(uint4*)(pBh + row * PB + kv * 16) = sh[vi];
                *(uint4*)(pBl + row * PB + kv * 16) = sl[vi];
            }
        }
        __syncthreads();
        if (!active) continue;

        #pragma unroll
        for (int kc = 0; kc < KC; kc++) {
            const uint32_t k0b = kc * 32;
            uint32_t Ah[4][4], Al[4][4], Bh[2][4], Bl[2][4];
            #pragma unroll
            for (int mt = 0; mt < 4; mt++) {
                uint32_t off = a_base + k0b + (uint32_t)(mt * 16) * PB;
                ldsm_x4(Ah[mt], sAh + off);
                ldsm_x4(Al[mt], sAl + off);
            }
            #pragma unroll
            for (int p = 0; p < 2; p++) {
                uint32_t off = b_base + k0b + (uint32_t)(p * 16) * PB;
                ldsm_x4(Bh[p], sBh + off);
                ldsm_x4(Bl[p], sBl + off);
            }
            #pragma unroll
            for (int mt = 0; mt < 4; mt++) {
                #pragma unroll
                for (int nt = 0; nt < 4; nt++) {
                    const int pr = nt >> 1, rr = (nt & 1) * 2;
                    mma16816(acc[mt][nt], Ah[mt], Bh[pr][rr], Bh[pr][rr + 1]);
                    mma16816(acc[mt][nt], Ah[mt], Bl[pr][rr], Bl[pr][rr + 1]);
                    mma16816(acc[mt][nt], Al[mt], Bh[pr][rr], Bh[pr][rr + 1]);
                }
            }
        }
    }

    // --- epilogue ---
    if (!active) return;
    #pragma unroll
    for (int mt = 0; mt < 4; mt++) {
        #pragma unroll
        for (int nt = 0; nt < 4; nt++) {
            const int cl = warpN * 32 + nt * 8 + (lane & 3) * 2;   // local oc (even)
            const int oc = ocb * 128 + cl;
            if (oc + 1 >= OC_total && oc >= OC_total) continue;
            const float b0 = bias[oc], b1 = bias[oc + 1];
            const int r0 = pixbase + warpM * 64 + mt * 16 + (lane >> 2);
            #pragma unroll
            for (int h = 0; h < 2; h++) {
                const int pix = r0 + h * 8;
                float v0 = acc[mt][nt][2 * h]     + b0;
                float v1 = acc[mt][nt][2 * h + 1] + b1;
                if (out_f32) {
                    float2 fv = make_float2(v0, v1);
                    *(float2*)(out_f32 + (size_t)pix * OC4 + oc) = fv;
                } else {
                    v0 = eluf(v0);
                    v1 = eluf(v1);
                    __nv_bfloat16 h0 = __float2bfloat16_rn(v0);
                    __nv_bfloat16 h1 = __float2bfloat16_rn(v1);
                    __nv_bfloat16 l0 = __float2bfloat16_rn(v0 - __bfloat162float(h0));
                    __nv_bfloat16 l1 = __float2bfloat16_rn(v1 - __bfloat162float(h1));
                    uint32_t hw = (uint32_t)__bfloat16_as_ushort(h0) | ((uint32_t)__bfloat16_as_ushort(h1) << 16);
                    uint32_t lw = (uint32_t)__bfloat16_as_ushort(l0) | ((uint32_t)__bfloat16_as_ushort(l1) << 16);
                    *(uint32_t*)(out_hi + (size_t)pix * 128 + cl) = hw;
                    *(uint32_t*)(out_lo + (size_t)pix * 128 + cl) = lw;
                }
            }
        }
    }
}

// ---------------------------------------------------------------------------
// expm kernel: per-pixel 16x16 Taylor expm, y2, log_det
// ---------------------------------------------------------------------------
__global__ __launch_bounds__(256)
void expm_kernel(const float* __restrict__ o,
                 const float* __restrict__ scale, const float* __restrict__ shift_p,
                 const float* __restrict__ rescale, const float* __restrict__ reshift,
                 float* __restrict__ out)
{
    __shared__ float sA[16][16][16];
    __shared__ float sX[16][16];
    __shared__ float sY[16][17];
    __shared__ float sTr[8];

    const int tid  = threadIdx.x;
    const int lane = tid & 31;
    const int warp = tid >> 5;
    const int half = lane >> 4;
    const int r    = lane & 15;
    const int pixB = warp * 2 + half;

    const int pix_base = blockIdx.x * 16;
    const int b  = pix_base >> 12;
    const int p  = pix_base & 4095;
    const int y  = p >> 6;
    const int x0 = p & 63;
    const int pix = pix_base + pixB;

    const float sc = scale[0], sp = shift_p[0], rs = rescale[0], rf = reshift[0];
    const float* op = o + (size_t)pix * OC4;

    float arow[16];
    #pragma unroll
    for (int j = 0; j < 16; j++) {
        float v = op[(j + 1) * 16 + r];
        arow[j] = rs * tanhf(sc * v + sp) + rf;
    }
    float tr = arow[r];

    #pragma unroll
    for (int j = 0; j < 16; j++) sA[pixB][r][j] = arow[j];
    sX[pixB][r] = g_x2t[(size_t)pix * 16 + r];
    __syncwarp();

    float term[16], acc[16];
    #pragma unroll
    for (int j = 0; j < 16; j++) {
        term[j] = arow[j];
        acc[j]  = arow[j] + (j == r ? 1.0f : 0.0f);
    }

    #pragma unroll 1
    for (int k = 2; k <= 18; k++) {
        float c[16];
        #pragma unroll
        for (int j = 0; j < 16; j++) c[j] = 0.0f;
        #pragma unroll
        for (int m = 0; m < 16; m++) {
            float t = term[m];
            #pragma unroll
            for (int j = 0; j < 16; j++) c[j] += t * sA[pixB][m][j];
        }
        float inv = 1.0f / (float)k;
        #pragma unroll
        for (int j = 0; j < 16; j++) { term[j] = c[j] * inv; acc[j] += term[j]; }
    }

    float y2 = 0.0f;
    #pragma unroll
    for (int j = 0; j < 16; j++) y2 += acc[j] * sX[pixB][j];
    y2 += op[r];
    sY[pixB][r] = y2;

    #pragma unroll
    for (int off = 16; off > 0; off >>= 1) tr += __shfl_down_sync(0xffffffffu, tr, off);
    if (lane == 0) sTr[warp] = tr;
    __syncthreads();
    if (tid == 0) {
        float s = 0.0f;
        #pragma unroll
        for (int w2 = 0; w2 < 8; w2++) s += sTr[w2];
        atomicAdd(out + (size_t)Bn * 32 * Hh * Ww + b, s);
    }

    const int c  = tid >> 4;
    const int p2 = tid & 15;
    out[((size_t)(b * 32 + 16 + c)) * (Hh * Ww) + y * Ww + x0 + p2] = sY[p2][c];
}

// ---------------------------------------------------------------------------
extern "C" void kernel_launch(void* const* d_in, const int* in_sizes, int n_in,
                              void* d_out, int out_size)
{
    const float* x       = (const float*)d_in[0];
    const float* scale   = (const float*)d_in[1];
    const float* shift_p = (const float*)d_in[2];
    const float* rescale = (const float*)d_in[3];
    const float* reshift = (const float*)d_in[4];
    const float* w0 = (const float*)d_in[5];
    const float* b0 = (const float*)d_in[6];
    const float* w1 = (const float*)d_in[7];
    const float* b1 = (const float*)d_in[8];
    const float* w2 = (const float*)d_in[9];
    const float* b2 = (const float*)d_in[10];
    const float* w3 = (const float*)d_in[11];
    const float* b3 = (const float*)d_in[12];
    float* out = (float*)d_out;

    __nv_bfloat16 *x1h, *x1l, *a0h, *a0l, *a1h, *a1l;
    __nv_bfloat16 *wb0h, *wb0l, *wb1h, *wb1l, *wb2h, *wb2l, *wb3h, *wb3l;
    float *x2t, *oB;
    cudaGetSymbolAddress((void**)&x1h, g_x1h);
    cudaGetSymbolAddress((void**)&x1l, g_x1l);
    cudaGetSymbolAddress((void**)&x2t, g_x2t);
    cudaGetSymbolAddress((void**)&a0h, g_a0h);
    cudaGetSymbolAddress((void**)&a0l, g_a0l);
    cudaGetSymbolAddress((void**)&a1h, g_a1h);
    cudaGetSymbolAddress((void**)&a1l, g_a1l);
    cudaGetSymbolAddress((void**)&oB,  g_o);
    cudaGetSymbolAddress((void**)&wb0h, g_wb0h);
    cudaGetSymbolAddress((void**)&wb0l, g_wb0l);
    cudaGetSymbolAddress((void**)&wb1h, g_wb1h);
    cudaGetSymbolAddress((void**)&wb1l, g_wb1l);
    cudaGetSymbolAddress((void**)&wb2h, g_wb2h);
    cudaGetSymbolAddress((void**)&wb2l, g_wb2l);
    cudaGetSymbolAddress((void**)&wb3h, g_wb3h);
    cudaGetSymbolAddress((void**)&wb3l, g_wb3l);

    const int SMEM0 = 4 * 128 * (16 + 8) * 2;     // 24576
    const int SMEM1 = 4 * 128 * (128 + 8) * 2;    // 139264
    cudaFuncSetAttribute(conv_mma_kernel<16>,  cudaFuncAttributeMaxDynamicSharedMemorySize, SMEM0);
    cudaFuncSetAttribute(conv_mma_kernel<128>, cudaFuncAttributeMaxDynamicSharedMemorySize, SMEM1);

    // 1) split / passthrough
    {
        int n = Bn * 32 * Hh * Ww;
        prep_kernel<<<(n + 255) / 256, 256>>>(x, out);
    }
    // 2) weight tiling (hi/lo bf16, plain tiles)
    {
        int n0 = 9 * 128 * 16;
        wprep_kernel<<<(n0 + 255) / 256, 256>>>(w0, wb0h, wb0l, HIDc, C1, n0);
        int n1 = 9 * 128 * 128;
        wprep_kernel<<<(n1 + 255) / 256, 256>>>(w1, wb1h, wb1l, HIDc, HIDc, n1);
        wprep_kernel<<<(n1 + 255) / 256, 256>>>(w2, wb2h, wb2l, HIDc, HIDc, n1);
        int n3 = 3 * 9 * 128 * 128;
        wprep_kernel<<<(n3 + 255) / 256, 256>>>(w3, wb3h, wb3l, OC4, HIDc, n3);
    }
    // 3) convs via mma.sync (hi/lo bf16 split precision)
    conv_mma_kernel<16><<<dim3(NPIX / 128, 1), 256, SMEM0>>>(
        x1h, x1l, wb0h, wb0l, b0, a0h, a0l, nullptr, HIDc);
    conv_mma_kernel<128><<<dim3(NPIX / 128, 1), 256, SMEM1>>>(
        a0h, a0l, wb1h, wb1l, b1, a1h, a1l, nullptr, HIDc);
    conv_mma_kernel<128><<<dim3(NPIX / 128, 1), 256, SMEM1>>>(
        a1h, a1l, wb2h, wb2l, b2, a0h, a0l, nullptr, HIDc);
    conv_mma_kernel<128><<<dim3(NPIX / 128, 3), 256, SMEM1>>>(
        a0h, a0l, wb3h, wb3l, b3, nullptr, nullptr, oB, OC4);
    // 4) expm + assembly + log_det
    expm_kernel<<<NPIX / 16, 256>>>(oB, scale, shift_p, rescale, reshift, out);

    (void)in_sizes; (void)n_in; (void)out_size;
}

// round 4
// speedup vs baseline: 6.4746x; 1.5813x over previous
#include <cuda_runtime.h>
#include <cuda_bf16.h>
#include <math.h>
#include <stdint.h>

// Shapes (fixed)
#define Bn   16
#define Hh   64
#define Ww   64
#define C1   16
#define C2   16
#define HIDc 128
#define OC4  272          // C2*(C2+1)
#define NPIX (Bn*Hh*Ww)   // 65536

// ---------------------------------------------------------------------------
__device__ __forceinline__ uint32_t smem_u32(const void* p) {
    uint32_t a;
    asm("{ .reg .u64 t; cvta.to.shared.u64 t, %1; cvt.u32.u64 %0, t; }" : "=r"(a) : "l"(p));
    return a;
}

__device__ __forceinline__ void ldsm_x4(uint32_t (&r)[4], uint32_t addr) {
    asm volatile("ldmatrix.sync.aligned.m8n8.x4.shared.b16 {%0,%1,%2,%3}, [%4];"
        : "=r"(r[0]), "=r"(r[1]), "=r"(r[2]), "=r"(r[3]) : "r"(addr));
}

__device__ __forceinline__ void mma16816(float (&d)[4], const uint32_t (&a)[4],
                                         uint32_t b0, uint32_t b1) {
    asm volatile("mma.sync.aligned.m16n8k16.row.col.f32.bf16.bf16.f32 "
        "{%0,%1,%2,%3}, {%4,%5,%6,%7}, {%8,%9}, {%0,%1,%2,%3};"
        : "+f"(d[0]), "+f"(d[1]), "+f"(d[2]), "+f"(d[3])
        : "r"(a[0]), "r"(a[1]), "r"(a[2]), "r"(a[3]), "r"(b0), "r"(b1));
}

__device__ __forceinline__ void cp16(uint32_t dst, const void* src, bool pred) {
    asm volatile("cp.async.cg.shared.global [%0], [%1], 16, %2;"
        :: "r"(dst), "l"(src), "r"(pred ? 16u : 0u) : "memory");
}
#define CP_COMMIT() asm volatile("cp.async.commit_group;" ::: "memory")
#define CP_WAIT0()  asm volatile("cp.async.wait_group 0;" ::: "memory")

__device__ __forceinline__ float eluf(float t) { return t > 0.0f ? t : expm1f(t); }

// ---------------- scratch (device globals) ----------------
__device__ __align__(16) __nv_bfloat16 g_x1h[NPIX * C1];
__device__ __align__(16) __nv_bfloat16 g_x1l[NPIX * C1];
__device__ __align__(16) float         g_x2t[NPIX * C2];
__device__ __align__(16) __nv_bfloat16 g_a0h[NPIX * HIDc];
__device__ __align__(16) __nv_bfloat16 g_a0l[NPIX * HIDc];
__device__ __align__(16) __nv_bfloat16 g_a1h[NPIX * HIDc];
__device__ __align__(16) __nv_bfloat16 g_a1l[NPIX * HIDc];
__device__ __align__(16) float         g_o  [(size_t)NPIX * OC4];
// pre-tiled weights, plain [tile][tap][128 oc][ICA] bf16, hi/lo
__device__ __align__(16) __nv_bfloat16 g_wb0h[9 * 128 * 16];
__device__ __align__(16) __nv_bfloat16 g_wb0l[9 * 128 * 16];
__device__ __align__(16) __nv_bfloat16 g_wb1h[9 * 128 * 128];
__device__ __align__(16) __nv_bfloat16 g_wb1l[9 * 128 * 128];
__device__ __align__(16) __nv_bfloat16 g_wb2h[9 * 128 * 128];
__device__ __align__(16) __nv_bfloat16 g_wb2l[9 * 128 * 128];
__device__ __align__(16) __nv_bfloat16 g_wb3h[3 * 9 * 128 * 128];
__device__ __align__(16) __nv_bfloat16 g_wb3l[3 * 9 * 128 * 128];

// ---------------------------------------------------------------------------
// prep: NCHW -> NHWC split (x1 as bf16 hi/lo, x2 fp32), passthrough, zero logdet
// ---------------------------------------------------------------------------
__global__ void prep_kernel(const float* __restrict__ x, float* __restrict__ out)
{
    int idx = blockIdx.x * blockDim.x + threadIdx.x;
    if (idx < Bn) out[(size_t)Bn * 32 * Hh * Ww + idx] = 0.0f;
    if (idx >= Bn * 32 * Hh * Ww) return;
    int b = idx >> 17;
    int c = (idx >> 12) & 31;
    int p = idx & 4095;
    float v = x[idx];
    int pix = (b << 12) + p;
    if (c < C1) {
        out[idx] = v;
        __nv_bfloat16 h = __float2bfloat16_rn(v);
        g_x1h[pix * C1 + c] = h;
        g_x1l[pix * C1 + c] = __float2bfloat16_rn(v - __bfloat162float(h));
    } else {
        g_x2t[pix * C2 + (c - C1)] = v;
    }
}

// ---------------------------------------------------------------------------
// wprep: w[OC][ICA][3][3] fp32 -> [tile][tap][128][ICA] bf16 hi/lo (plain)
// ---------------------------------------------------------------------------
__global__ void wprep_kernel(const float* __restrict__ w,
                             __nv_bfloat16* __restrict__ dh,
                             __nv_bfloat16* __restrict__ dl,
                             int OC, int ICA, int total)
{
    int idx = blockIdx.x * blockDim.x + threadIdx.x;
    if (idx >= total) return;
    int k   = idx % ICA;
    int row = (idx / ICA) & 127;
    int tt  = idx / (ICA * 128);
    int tap  = tt % 9;
    int tile = tt / 9;
    int oc = tile * 128 + row;
    float v = (oc < OC) ? w[((size_t)oc * ICA + k) * 9 + tap] : 0.0f;
    __nv_bfloat16 h = __float2bfloat16_rn(v);
    dh[idx] = h;
    dl[idx] = __float2bfloat16_rn(v - __bfloat162float(h));
}

// ---------------------------------------------------------------------------
// Implicit 3x3 conv via mma.sync, A halo resident in SMEM for all 9 taps.
// CTA = 128 px (2 image rows) x 128 oc, 8 warps (2M x 4N).
// A halo: 4 rows x 66 cols staged ONCE via cp.async. B staged per tap.
// ---------------------------------------------------------------------------
template<int ICA>
__global__ __launch_bounds__(256, 1)
void conv_mma_kernel(const __nv_bfloat16* __restrict__ in_hi,
                     const __nv_bfloat16* __restrict__ in_lo,
                     const __nv_bfloat16* __restrict__ wb_hi,
                     const __nv_bfloat16* __restrict__ wb_lo,
                     const float* __restrict__ bias,
                     __nv_bfloat16* __restrict__ out_hi,
                     __nv_bfloat16* __restrict__ out_lo,
                     float* __restrict__ out_f32,
                     int OC_total)
{
    constexpr int PITCH = ICA + 8;       // elements
    constexpr int PB    = PITCH * 2;     // bytes per row
    constexpr int AROWS = 4 * 66;        // halo: 4 image rows x 66 cols
    constexpr int ATILE = AROWS * PB;
    constexpr int BTILE = 128 * PB;
    constexpr int VPA   = ICA / 8;       // 16B vectors per row
    constexpr int KC    = ICA / 16;      // k16 steps per tap

    extern __shared__ char smem[];
    const uint32_t sAh = smem_u32(smem);
    const uint32_t sAl = sAh + ATILE;
    const uint32_t sBh = sAl + ATILE;
    const uint32_t sBl = sBh + BTILE;

    const int tid  = threadIdx.x;
    const int lane = tid & 31;
    const int warp = tid >> 5;
    const int warpM = warp & 1;
    const int warpN = warp >> 1;

    const int pixbase = blockIdx.x * 128;
    const int b  = pixbase >> 12;
    const int y0 = (pixbase & 4095) >> 6;
    const int ocb = blockIdx.y;
    const bool active = (ocb * 128 + warpN * 32) < OC_total;

    float acc[4][4][4];
    #pragma unroll
    for (int mt = 0; mt < 4; mt++)
        #pragma unroll
        for (int nt = 0; nt < 4; nt++)
            #pragma unroll
            for (int q = 0; q < 4; q++) acc[mt][nt][q] = 0.0f;

    // ---- stage A halo once (hi+lo) + B tap0, all via cp.async ----
    for (int vi = tid; vi < AROWS * VPA; vi += 256) {
        int row = vi / VPA;
        int kv  = vi % VPA;
        int yy  = y0 + row / 66 - 1;
        int xx  = (row % 66) - 1;
        bool ok = (yy >= 0 && yy < Hh && xx >= 0 && xx < Ww);
        size_t src = ok ? (((size_t)((b << 12) + (yy << 6) + xx)) * ICA + kv * 8) : 0;
        uint32_t dst = row * PB + kv * 16;
        cp16(sAh + dst, in_hi + src, ok);
        cp16(sAl + dst, in_lo + src, ok);
    }
    {
        const char* bh = (const char*)(wb_hi + ((size_t)(ocb * 9 + 0)) * 128 * ICA);
        const char* bl = (const char*)(wb_lo + ((size_t)(ocb * 9 + 0)) * 128 * ICA);
        for (int vi = tid; vi < 128 * VPA; vi += 256) {
            int row = vi / VPA, kv = vi % VPA;
            uint32_t dst = row * PB + kv * 16;
            cp16(sBh + dst, bh + vi * 16, true);
            cp16(sBl + dst, bl + vi * 16, true);
        }
    }
    CP_COMMIT();
    CP_WAIT0();
    __syncthreads();

    // per-lane ldmatrix base offsets
    const uint32_t a_base = (uint32_t)((warpM + 1) * 66 + (lane & 15) + 1) * PB + (uint32_t)(lane & 16);
    const uint32_t b_base = (uint32_t)(warpN * 32 + (lane & 7) + ((lane & 16) >> 1)) * PB
                          + (uint32_t)((lane & 8) << 1);

    for (int tap = 0; tap < 9; tap++) {
        if (tap > 0) {
            __syncthreads();   // everyone done with previous B
            const char* bh = (const char*)(wb_hi + ((size_t)(ocb * 9 + tap)) * 128 * ICA);
            const char* bl = (const char*)(wb_lo + ((size_t)(ocb * 9 + tap)) * 128 * ICA);
            for (int vi = tid; vi < 128 * VPA; vi += 256) {
                int row = vi / VPA, kv = vi % VPA;
                uint32_t dst = row * PB + kv * 16;
                cp16(sBh + dst, bh + vi * 16, true);
                cp16(sBl + dst, bl + vi * 16, true);
            }
            CP_COMMIT();
            CP_WAIT0();
            __syncthreads();
        }
        if (!active) continue;

        const int dy = tap / 3 - 1, dx = tap % 3 - 1;
        const uint32_t tapoff = (uint32_t)((dy * 66 + dx) * PB);

        #pragma unroll
        for (int kc = 0; kc < KC; kc++) {
            const uint32_t k0b = kc * 32;
            uint32_t Ah[4][4], Al[4][4], Bh[2][4], Bl[2][4];
            #pragma unroll
            for (int mt = 0; mt < 4; mt++) {
                uint32_t off = a_base + tapoff + k0b + (uint32_t)(mt * 16) * PB;
                ldsm_x4(Ah[mt], sAh + off);
                ldsm_x4(Al[mt], sAl + off);
            }
            #pragma unroll
            for (int p = 0; p < 2; p++) {
                uint32_t off = b_base + k0b + (uint32_t)(p * 16) * PB;
                ldsm_x4(Bh[p], sBh + off);
                ldsm_x4(Bl[p], sBl + off);
            }
            #pragma unroll
            for (int mt = 0; mt < 4; mt++) {
                #pragma unroll
                for (int nt = 0; nt < 4; nt++) {
                    const int pr = nt >> 1, rr = (nt & 1) * 2;
                    mma16816(acc[mt][nt], Ah[mt], Bh[pr][rr], Bh[pr][rr + 1]);
                    mma16816(acc[mt][nt], Ah[mt], Bl[pr][rr], Bl[pr][rr + 1]);
                    mma16816(acc[mt][nt], Al[mt], Bh[pr][rr], Bh[pr][rr + 1]);
                }
            }
        }
    }

    // --- epilogue ---
    if (!active) return;
    #pragma unroll
    for (int mt = 0; mt < 4; mt++) {
        #pragma unroll
        for (int nt = 0; nt < 4; nt++) {
            const int cl = warpN * 32 + nt * 8 + (lane & 3) * 2;   // local oc (even)
            const int oc = ocb * 128 + cl;
            if (oc >= OC_total) continue;
            const float b0 = bias[oc], b1 = bias[oc + 1];
            const int r0 = pixbase + warpM * 64 + mt * 16 + (lane >> 2);
            #pragma unroll
            for (int h = 0; h < 2; h++) {
                const int pix = r0 + h * 8;
                float v0 = acc[mt][nt][2 * h]     + b0;
                float v1 = acc[mt][nt][2 * h + 1] + b1;
                if (out_f32) {
                    float2 fv = make_float2(v0, v1);
                    *(float2*)(out_f32 + (size_t)pix * OC4 + oc) = fv;
                } else {
                    v0 = eluf(v0);
                    v1 = eluf(v1);
                    __nv_bfloat16 h0 = __float2bfloat16_rn(v0);
                    __nv_bfloat16 h1 = __float2bfloat16_rn(v1);
                    __nv_bfloat16 l0 = __float2bfloat16_rn(v0 - __bfloat162float(h0));
                    __nv_bfloat16 l1 = __float2bfloat16_rn(v1 - __bfloat162float(h1));
                    uint32_t hw = (uint32_t)__bfloat16_as_ushort(h0) | ((uint32_t)__bfloat16_as_ushort(h1) << 16);
                    uint32_t lw = (uint32_t)__bfloat16_as_ushort(l0) | ((uint32_t)__bfloat16_as_ushort(l1) << 16);
                    *(uint32_t*)(out_hi + (size_t)pix * 128 + cl) = hw;
                    *(uint32_t*)(out_lo + (size_t)pix * 128 + cl) = lw;
                }
            }
        }
    }
}

// ---------------------------------------------------------------------------
// expm kernel, MATVEC form: y2 = sum_k A^k x2 / k!, 18 matvecs per pixel.
// Block = 256 thr = 16 pixels, half-warp per pixel, lane = vector component.
// ---------------------------------------------------------------------------
__global__ __launch_bounds__(256)
void expm_kernel(const float* __restrict__ o,
                 const float* __restrict__ scale, const float* __restrict__ shift_p,
                 const float* __restrict__ rescale, const float* __restrict__ reshift,
                 float* __restrict__ out)
{
    __shared__ float sT[16][20];   // t vectors (padded, 16B-aligned rows)
    __shared__ float sY[16][17];
    __shared__ float sTr[8];

    const int tid  = threadIdx.x;
    const int lane = tid & 31;
    const int warp = tid >> 5;
    const int half = lane >> 4;
    const int r    = lane & 15;
    const int pixB = warp * 2 + half;

    const int pix_base = blockIdx.x * 16;
    const int b  = pix_base >> 12;
    const int p  = pix_base & 4095;
    const int y  = p >> 6;
    const int x0 = p & 63;
    const int pix = pix_base + pixB;

    const float sc = scale[0], sp = shift_p[0], rs = rescale[0], rf = reshift[0];
    const float* op = o + (size_t)pix * OC4;

    // A row r: A[r][j] = rs*tanh(sc*o[(j+1)*16+r]+sp)+rf
    float arow[16];
    #pragma unroll
    for (int j = 0; j < 16; j++) {
        float v = op[(j + 1) * 16 + r];
        arow[j] = rs * tanhf(sc * v + sp) + rf;
    }
    float tr = arow[r];

    const float x2v = g_x2t[(size_t)pix * 16 + r];
    sT[pixB][r] = x2v;
    float yacc = x2v;                    // k=0 (identity) term
    __syncwarp();

    #pragma unroll
    for (int k = 1; k <= 18; k++) {
        float s = 0.0f;
        #pragma unroll
        for (int j = 0; j < 16; j++) s += arow[j] * sT[pixB][j];
        s *= (1.0f / (float)k);
        __syncwarp();
        sT[pixB][r] = s;
        __syncwarp();
        yacc += s;
    }

    sY[pixB][r] = yacc + op[r];          // + shift channel r

    #pragma unroll
    for (int off = 16; off > 0; off >>= 1) tr += __shfl_down_sync(0xffffffffu, tr, off);
    if (lane == 0) sTr[warp] = tr;
    __syncthreads();
    if (tid == 0) {
        float s = 0.0f;
        #pragma unroll
        for (int w2 = 0; w2 < 8; w2++) s += sTr[w2];
        atomicAdd(out + (size_t)Bn * 32 * Hh * Ww + b, s);
    }

    const int c  = tid >> 4;
    const int p2 = tid & 15;
    out[((size_t)(b * 32 + 16 + c)) * (Hh * Ww) + y * Ww + x0 + p2] = sY[p2][c];
}

// ---------------------------------------------------------------------------
extern "C" void kernel_launch(void* const* d_in, const int* in_sizes, int n_in,
                              void* d_out, int out_size)
{
    const float* x       = (const float*)d_in[0];
    const float* scale   = (const float*)d_in[1];
    const float* shift_p = (const float*)d_in[2];
    const float* rescale = (const float*)d_in[3];
    const float* reshift = (const float*)d_in[4];
    const float* w0 = (const float*)d_in[5];
    const float* b0 = (const float*)d_in[6];
    const float* w1 = (const float*)d_in[7];
    const float* b1 = (const float*)d_in[8];
    const float* w2 = (const float*)d_in[9];
    const float* b2 = (const float*)d_in[10];
    const float* w3 = (const float*)d_in[11];
    const float* b3 = (const float*)d_in[12];
    float* out = (float*)d_out;

    __nv_bfloat16 *x1h, *x1l, *a0h, *a0l, *a1h, *a1l;
    __nv_bfloat16 *wb0h, *wb0l, *wb1h, *wb1l, *wb2h, *wb2l, *wb3h, *wb3l;
    float *x2t, *oB;
    cudaGetSymbolAddress((void**)&x1h, g_x1h);
    cudaGetSymbolAddress((void**)&x1l, g_x1l);
    cudaGetSymbolAddress((void**)&x2t, g_x2t);
    cudaGetSymbolAddress((void**)&a0h, g_a0h);
    cudaGetSymbolAddress((void**)&a0l, g_a0l);
    cudaGetSymbolAddress((void**)&a1h, g_a1h);
    cudaGetSymbolAddress((void**)&a1l, g_a1l);
    cudaGetSymbolAddress((void**)&oB,  g_o);
    cudaGetSymbolAddress((void**)&wb0h, g_wb0h);
    cudaGetSymbolAddress((void**)&wb0l, g_wb0l);
    cudaGetSymbolAddress((void**)&wb1h, g_wb1h);
    cudaGetSymbolAddress((void**)&wb1l, g_wb1l);
    cudaGetSymbolAddress((void**)&wb2h, g_wb2h);
    cudaGetSymbolAddress((void**)&wb2l, g_wb2l);
    cudaGetSymbolAddress((void**)&wb3h, g_wb3h);
    cudaGetSymbolAddress((void**)&wb3l, g_wb3l);

    // SMEM: A halo (4*66 rows) hi/lo + B tile (128 rows) hi/lo, pitch ICA+8
    const int SMEM0 = (4 * 66 + 128) * (16 + 8) * 2 * 2;     //  37,632
    const int SMEM1 = (4 * 66 + 128) * (128 + 8) * 2 * 2;    // 213,248
    cudaFuncSetAttribute(conv_mma_kernel<16>,  cudaFuncAttributeMaxDynamicSharedMemorySize, SMEM0);
    cudaFuncSetAttribute(conv_mma_kernel<128>, cudaFuncAttributeMaxDynamicSharedMemorySize, SMEM1);

    // 1) split / passthrough
    {
        int n = Bn * 32 * Hh * Ww;
        prep_kernel<<<(n + 255) / 256, 256>>>(x, out);
    }
    // 2) weight tiling (hi/lo bf16, plain tiles)
    {
        int n0 = 9 * 128 * 16;
        wprep_kernel<<<(n0 + 255) / 256, 256>>>(w0, wb0h, wb0l, HIDc, C1, n0);
        int n1 = 9 * 128 * 128;
        wprep_kernel<<<(n1 + 255) / 256, 256>>>(w1, wb1h, wb1l, HIDc, HIDc, n1);
        wprep_kernel<<<(n1 + 255) / 256, 256>>>(w2, wb2h, wb2l, HIDc, HIDc, n1);
        int n3 = 3 * 9 * 128 * 128;
        wprep_kernel<<<(n3 + 255) / 256, 256>>>(w3, wb3h, wb3l, OC4, HIDc, n3);
    }
    // 3) convs via mma.sync (hi/lo bf16 split precision), A-halo resident
    conv_mma_kernel<16><<<dim3(NPIX / 128, 1), 256, SMEM0>>>(
        x1h, x1l, wb0h, wb0l, b0, a0h, a0l, nullptr, HIDc);
    conv_mma_kernel<128><<<dim3(NPIX / 128, 1), 256, SMEM1>>>(
        a0h, a0l, wb1h, wb1l, b1, a1h, a1l, nullptr, HIDc);
    conv_mma_kernel<128><<<dim3(NPIX / 128, 1), 256, SMEM1>>>(
        a1h, a1l, wb2h, wb2l, b2, a0h, a0l, nullptr, HIDc);
    conv_mma_kernel<128><<<dim3(NPIX / 128, 3), 256, SMEM1>>>(
        a0h, a0l, wb3h, wb3l, b3, nullptr, nullptr, oB, OC4);
    // 4) expm (matvec Taylor) + assembly + log_det
    expm_kernel<<<NPIX / 16, 256>>>(oB, scale, shift_p, rescale, reshift, out);

    (void)in_sizes; (void)n_in; (void)out_size;
}

// round 6
// speedup vs baseline: 6.9300x; 1.0703x over previous
#include <cuda_runtime.h>
#include <cuda_bf16.h>
#include <math.h>
#include <stdint.h>

// Shapes (fixed)
#define Bn   16
#define Hh   64
#define Ww   64
#define C1   16
#define C2   16
#define HIDc 128
#define OC4  272          // C2*(C2+1)
#define NPIX (Bn*Hh*Ww)   // 65536

// ---------------------------------------------------------------------------
__device__ __forceinline__ uint32_t smem_u32(const void* p) {
    uint32_t a;
    asm("{ .reg .u64 t; cvta.to.shared.u64 t, %1; cvt.u32.u64 %0, t; }" : "=r"(a) : "l"(p));
    return a;
}

__device__ __forceinline__ void ldsm_x4(uint32_t (&r)[4], uint32_t addr) {
    asm volatile("ldmatrix.sync.aligned.m8n8.x4.shared.b16 {%0,%1,%2,%3}, [%4];"
        : "=r"(r[0]), "=r"(r[1]), "=r"(r[2]), "=r"(r[3]) : "r"(addr));
}

__device__ __forceinline__ void mma16816(float (&d)[4], const uint32_t (&a)[4],
                                         uint32_t b0, uint32_t b1) {
    asm volatile("mma.sync.aligned.m16n8k16.row.col.f32.bf16.bf16.f32 "
        "{%0,%1,%2,%3}, {%4,%5,%6,%7}, {%8,%9}, {%0,%1,%2,%3};"
        : "+f"(d[0]), "+f"(d[1]), "+f"(d[2]), "+f"(d[3])
        : "r"(a[0]), "r"(a[1]), "r"(a[2]), "r"(a[3]), "r"(b0), "r"(b1));
}

__device__ __forceinline__ void cp16(uint32_t dst, const void* src, bool pred) {
    asm volatile("cp.async.cg.shared.global [%0], [%1], 16, %2;"
        :: "r"(dst), "l"(src), "r"(pred ? 16u : 0u) : "memory");
}
#define CP_COMMIT() asm volatile("cp.async.commit_group;" ::: "memory")
#define CP_WAIT0()  asm volatile("cp.async.wait_group 0;" ::: "memory")
#define CP_WAIT1()  asm volatile("cp.async.wait_group 1;" ::: "memory")

__device__ __forceinline__ float eluf(float t) { return t > 0.0f ? t : expm1f(t); }

// ---------------- scratch (device globals) ----------------
__device__ __align__(16) __nv_bfloat16 g_x1h[NPIX * C1];
__device__ __align__(16) __nv_bfloat16 g_x1l[NPIX * C1];
__device__ __align__(16) float         g_x2t[NPIX * C2];
__device__ __align__(16) __nv_bfloat16 g_a0h[NPIX * HIDc];
__device__ __align__(16) __nv_bfloat16 g_a0l[NPIX * HIDc];
__device__ __align__(16) __nv_bfloat16 g_a1h[NPIX * HIDc];
__device__ __align__(16) __nv_bfloat16 g_a1l[NPIX * HIDc];
__device__ __align__(16) float         g_o  [(size_t)NPIX * OC4];
// pre-tiled weights: [tile64][tap][64 oc][ICA] bf16, hi/lo
__device__ __align__(16) __nv_bfloat16 g_wb0h[2 * 9 * 64 * 16];
__device__ __align__(16) __nv_bfloat16 g_wb0l[2 * 9 * 64 * 16];
__device__ __align__(16) __nv_bfloat16 g_wb1h[2 * 9 * 64 * 128];
__device__ __align__(16) __nv_bfloat16 g_wb1l[2 * 9 * 64 * 128];
__device__ __align__(16) __nv_bfloat16 g_wb2h[2 * 9 * 64 * 128];
__device__ __align__(16) __nv_bfloat16 g_wb2l[2 * 9 * 64 * 128];
__device__ __align__(16) __nv_bfloat16 g_wb3h[5 * 9 * 64 * 128];
__device__ __align__(16) __nv_bfloat16 g_wb3l[5 * 9 * 64 * 128];

// ---------------------------------------------------------------------------
// prep: NCHW -> NHWC split (x1 as bf16 hi/lo, x2 fp32), passthrough, zero logdet
// ---------------------------------------------------------------------------
__global__ void prep_kernel(const float* __restrict__ x, float* __restrict__ out)
{
    int idx = blockIdx.x * blockDim.x + threadIdx.x;
    if (idx < Bn) out[(size_t)Bn * 32 * Hh * Ww + idx] = 0.0f;
    if (idx >= Bn * 32 * Hh * Ww) return;
    int b = idx >> 17;
    int c = (idx >> 12) & 31;
    int p = idx & 4095;
    float v = x[idx];
    int pix = (b << 12) + p;
    if (c < C1) {
        out[idx] = v;
        __nv_bfloat16 h = __float2bfloat16_rn(v);
        g_x1h[pix * C1 + c] = h;
        g_x1l[pix * C1 + c] = __float2bfloat16_rn(v - __bfloat162float(h));
    } else {
        g_x2t[pix * C2 + (c - C1)] = v;
    }
}

// ---------------------------------------------------------------------------
// wprep: w[OC][ICA][3][3] fp32 -> [tile64][tap][64][ICA] bf16 hi/lo
// ---------------------------------------------------------------------------
__global__ void wprep_kernel(const float* __restrict__ w,
                             __nv_bfloat16* __restrict__ dh,
                             __nv_bfloat16* __restrict__ dl,
                             int OC, int ICA, int total)
{
    int idx = blockIdx.x * blockDim.x + threadIdx.x;
    if (idx >= total) return;
    int k   = idx % ICA;
    int row = (idx / ICA) & 63;
    int tt  = idx / (ICA * 64);
    int tap  = tt % 9;
    int tile = tt / 9;
    int oc = tile * 64 + row;
    float v = (oc < OC) ? w[((size_t)oc * ICA + k) * 9 + tap] : 0.0f;
    __nv_bfloat16 h = __float2bfloat16_rn(v);
    dh[idx] = h;
    dl[idx] = __float2bfloat16_rn(v - __bfloat162float(h));
}

// ---------------------------------------------------------------------------
// B-tile stager: one tap (64 rows x ICA) hi+lo into padded SMEM via cp.async
// ---------------------------------------------------------------------------
template<int ICA>
__device__ __forceinline__ void stage_B(uint32_t dsth, uint32_t dstl,
                                        const __nv_bfloat16* __restrict__ wh,
                                        const __nv_bfloat16* __restrict__ wl,
                                        int tid)
{
    constexpr int VPA = ICA / 8;
    constexpr int PB  = (ICA + 8) * 2;
    const char* bh = (const char*)wh;
    const char* bl = (const char*)wl;
    for (int vi = tid; vi < 64 * VPA; vi += 256) {
        int row = vi / VPA, kv = vi % VPA;
        uint32_t d = row * PB + kv * 16;
        cp16(dsth + d, bh + vi * 16, true);
        cp16(dstl + d, bl + vi * 16, true);
    }
}

// ---------------------------------------------------------------------------
// Implicit 3x3 conv via mma.sync; A halo resident, B double-buffered pipeline.
// CTA = 128 px (2 image rows) x 64 oc, 8 warps (4M x 2N), warp = 32px x 32oc.
// ---------------------------------------------------------------------------
template<int ICA>
__global__ __launch_bounds__(256, 1)
void conv_mma_kernel(const __nv_bfloat16* __restrict__ in_hi,
                     const __nv_bfloat16* __restrict__ in_lo,
                     const __nv_bfloat16* __restrict__ wb_hi,
                     const __nv_bfloat16* __restrict__ wb_lo,
                     const float* __restrict__ bias,
                     __nv_bfloat16* __restrict__ out_hi,
                     __nv_bfloat16* __restrict__ out_lo,
                     float* __restrict__ out_f32,
                     int OC_total)
{
    constexpr int PITCH = ICA + 8;
    constexpr int PB    = PITCH * 2;
    constexpr int AROWS = 4 * 66;
    constexpr int ATILE = AROWS * PB;
    constexpr int BTILE = 64 * PB;          // one buf, one precision
    constexpr int VPA   = ICA / 8;
    constexpr int KC    = ICA / 16;

    extern __shared__ char smem[];
    const uint32_t sAh = smem_u32(smem);
    const uint32_t sAl = sAh + ATILE;
    const uint32_t sB  = sAl + ATILE;       // [buf][hi|lo]

    const int tid  = threadIdx.x;
    const int lane = tid & 31;
    const int warp = tid >> 5;
    const int warpN = warp & 1;             // 2 N tiles of 32 oc
    const int warpM = warp >> 1;            // 4 M tiles of 32 px

    const int pixbase = blockIdx.x * 128;
    const int b  = pixbase >> 12;
    const int y0 = (pixbase & 4095) >> 6;
    const int ocb = blockIdx.y;
    const bool active = (ocb * 64 + warpN * 32) < OC_total;
    const size_t wbase = (size_t)ocb * 9 * (64 * ICA);

    float acc[2][4][4];
    #pragma unroll
    for (int mt = 0; mt < 2; mt++)
        #pragma unroll
        for (int nt = 0; nt < 4; nt++)
            #pragma unroll
            for (int q = 0; q < 4; q++) acc[mt][nt][q] = 0.0f;

    // ---- prologue: A halo + B[0] (group0), B[1] (group1) ----
    for (int vi = tid; vi < AROWS * VPA; vi += 256) {
        int row = vi / VPA;
        int kv  = vi % VPA;
        int yy  = y0 + row / 66 - 1;
        int xx  = (row % 66) - 1;
        bool ok = (yy >= 0 && yy < Hh && xx >= 0 && xx < Ww);
        size_t src = ok ? (((size_t)((b << 12) + (yy << 6) + xx)) * ICA + kv * 8) : 0;
        uint32_t dst = row * PB + kv * 16;
        cp16(sAh + dst, in_hi + src, ok);
        cp16(sAl + dst, in_lo + src, ok);
    }
    stage_B<ICA>(sB, sB + BTILE, wb_hi + wbase, wb_lo + wbase, tid);
    CP_COMMIT();
    stage_B<ICA>(sB + 2 * BTILE, sB + 3 * BTILE,
                 wb_hi + wbase + 64 * ICA, wb_lo + wbase + 64 * ICA, tid);
    CP_COMMIT();
    CP_WAIT1();
    __syncthreads();

    // per-lane ldmatrix base offsets
    const uint32_t a_base = (uint32_t)(((warpM >> 1) + 1) * 66
                          + (warpM & 1) * 32 + (lane & 15) + 1) * PB
                          + (uint32_t)(lane & 16);
    const uint32_t b_base = (uint32_t)(warpN * 32 + (lane & 7) + ((lane & 16) >> 1)) * PB
                          + (uint32_t)((lane & 8) << 1);

    for (int tap = 0; tap < 9; tap++) {
        const uint32_t bufh = sB + (uint32_t)(tap & 1) * (2 * BTILE);
        const uint32_t bufl = bufh + BTILE;

        if (active) {
            const int dy = tap / 3 - 1, dx = tap % 3 - 1;
            const uint32_t tapoff = (uint32_t)((dy * 66 + dx) * PB);
            #pragma unroll
            for (int kc = 0; kc < KC; kc++) {
                const uint32_t k0b = kc * 32;
                uint32_t Ah[2][4], Al[2][4], Bh[2][4], Bl[2][4];
                #pragma unroll
                for (int mt = 0; mt < 2; mt++) {
                    uint32_t off = a_base + tapoff + k0b + (uint32_t)(mt * 16) * PB;
                    ldsm_x4(Ah[mt], sAh + off);
                    ldsm_x4(Al[mt], sAl + off);
                }
                #pragma unroll
                for (int p = 0; p < 2; p++) {
                    uint32_t off = b_base + k0b + (uint32_t)(p * 16) * PB;
                    ldsm_x4(Bh[p], bufh + off);
                    ldsm_x4(Bl[p], bufl + off);
                }
                #pragma unroll
                for (int mt = 0; mt < 2; mt++) {
                    #pragma unroll
                    for (int nt = 0; nt < 4; nt++) {
                        const int pr = nt >> 1, rr = (nt & 1) * 2;
                        mma16816(acc[mt][nt], Ah[mt], Bh[pr][rr], Bh[pr][rr + 1]);
                        mma16816(acc[mt][nt], Ah[mt], Bl[pr][rr], Bl[pr][rr + 1]);
                        mma16816(acc[mt][nt], Al[mt], Bh[pr][rr], Bh[pr][rr + 1]);
                    }
                }
            }
        }
        __syncthreads();   // all warps done reading buf[tap&1]
        if (tap + 2 <= 8) {
            uint32_t nbh = sB + (uint32_t)(tap & 1) * (2 * BTILE);
            stage_B<ICA>(nbh, nbh + BTILE,
                         wb_hi + wbase + (size_t)(tap + 2) * 64 * ICA,
                         wb_lo + wbase + (size_t)(tap + 2) * 64 * ICA, tid);
            CP_COMMIT();
            CP_WAIT1();    // B[tap+1] complete (only B[tap+2] may pend)
        } else {
            CP_WAIT0();
        }
        __syncthreads();
    }

    // --- epilogue ---
    if (!active) return;
    #pragma unroll
    for (int mt = 0; mt < 2; mt++) {
        #pragma unroll
        for (int nt = 0; nt < 4; nt++) {
            const int cl = warpN * 32 + nt * 8 + (lane & 3) * 2;   // local oc (even)
            const int oc = ocb * 64 + cl;                          // global oc
            if (oc >= OC_total) continue;
            const float b0 = bias[oc], b1 = bias[oc + 1];
            const int r0 = pixbase + (warpM >> 1) * 64 + (warpM & 1) * 32
                         + mt * 16 + (lane >> 2);
            #pragma unroll
            for (int h = 0; h < 2; h++) {
                const int pix = r0 + h * 8;
                float v0 = acc[mt][nt][2 * h]     + b0;
                float v1 = acc[mt][nt][2 * h + 1] + b1;
                if (out_f32) {
                    float2 fv = make_float2(v0, v1);
                    *(float2*)(out_f32 + (size_t)pix * OC4 + oc) = fv;
                } else {
                    v0 = eluf(v0);
                    v1 = eluf(v1);
                    __nv_bfloat16 h0 = __float2bfloat16_rn(v0);
                    __nv_bfloat16 h1 = __float2bfloat16_rn(v1);
                    __nv_bfloat16 l0 = __float2bfloat16_rn(v0 - __bfloat162float(h0));
                    __nv_bfloat16 l1 = __float2bfloat16_rn(v1 - __bfloat162float(h1));
                    uint32_t hw = (uint32_t)__bfloat16_as_ushort(h0) | ((uint32_t)__bfloat16_as_ushort(h1) << 16);
                    uint32_t lw = (uint32_t)__bfloat16_as_ushort(l0) | ((uint32_t)__bfloat16_as_ushort(l1) << 16);
                    *(uint32_t*)(out_hi + (size_t)pix * 128 + oc) = hw;   // FIX: global oc
                    *(uint32_t*)(out_lo + (size_t)pix * 128 + oc) = lw;   // FIX: global oc
                }
            }
        }
    }
}

// ---------------------------------------------------------------------------
// expm kernel, MATVEC form: y2 = sum_k A^k x2 / k!, 18 matvecs per pixel.
// ---------------------------------------------------------------------------
__global__ __launch_bounds__(256)
void expm_kernel(const float* __restrict__ o,
                 const float* __restrict__ scale, const float* __restrict__ shift_p,
                 const float* __restrict__ rescale, const float* __restrict__ reshift,
                 float* __restrict__ out)
{
    __shared__ float sT[16][20];
    __shared__ float sY[16][17];
    __shared__ float sTr[8];

    const int tid  = threadIdx.x;
    const int lane = tid & 31;
    const int warp = tid >> 5;
    const int half = lane >> 4;
    const int r    = lane & 15;
    const int pixB = warp * 2 + half;

    const int pix_base = blockIdx.x * 16;
    const int b  = pix_base >> 12;
    const int p  = pix_base & 4095;
    const int y  = p >> 6;
    const int x0 = p & 63;
    const int pix = pix_base + pixB;

    const float sc = scale[0], sp = shift_p[0], rs = rescale[0], rf = reshift[0];
    const float* op = o + (size_t)pix * OC4;

    float arow[16];
    #pragma unroll
    for (int j = 0; j < 16; j++) {
        float v = op[(j + 1) * 16 + r];
        arow[j] = rs * tanhf(sc * v + sp) + rf;
    }
    float tr = arow[r];

    const float x2v = g_x2t[(size_t)pix * 16 + r];
    sT[pixB][r] = x2v;
    float yacc = x2v;
    __syncwarp();

    #pragma unroll
    for (int k = 1; k <= 18; k++) {
        float s = 0.0f;
        #pragma unroll
        for (int j = 0; j < 16; j++) s += arow[j] * sT[pixB][j];
        s *= (1.0f / (float)k);
        __syncwarp();
        sT[pixB][r] = s;
        __syncwarp();
        yacc += s;
    }

    sY[pixB][r] = yacc + op[r];

    #pragma unroll
    for (int off = 16; off > 0; off >>= 1) tr += __shfl_down_sync(0xffffffffu, tr, off);
    if (lane == 0) sTr[warp] = tr;
    __syncthreads();
    if (tid == 0) {
        float s = 0.0f;
        #pragma unroll
        for (int w2 = 0; w2 < 8; w2++) s += sTr[w2];
        atomicAdd(out + (size_t)Bn * 32 * Hh * Ww + b, s);
    }

    const int c  = tid >> 4;
    const int p2 = tid & 15;
    out[((size_t)(b * 32 + 16 + c)) * (Hh * Ww) + y * Ww + x0 + p2] = sY[p2][c];
}

// ---------------------------------------------------------------------------
extern "C" void kernel_launch(void* const* d_in, const int* in_sizes, int n_in,
                              void* d_out, int out_size)
{
    const float* x       = (const float*)d_in[0];
    const float* scale   = (const float*)d_in[1];
    const float* shift_p = (const float*)d_in[2];
    const float* rescale = (const float*)d_in[3];
    const float* reshift = (const float*)d_in[4];
    const float* w0 = (const float*)d_in[5];
    const float* b0 = (const float*)d_in[6];
    const float* w1 = (const float*)d_in[7];
    const float* b1 = (const float*)d_in[8];
    const float* w2 = (const float*)d_in[9];
    const float* b2 = (const float*)d_in[10];
    const float* w3 = (const float*)d_in[11];
    const float* b3 = (const float*)d_in[12];
    float* out = (float*)d_out;

    __nv_bfloat16 *x1h, *x1l, *a0h, *a0l, *a1h, *a1l;
    __nv_bfloat16 *wb0h, *wb0l, *wb1h, *wb1l, *wb2h, *wb2l, *wb3h, *wb3l;
    float *x2t, *oB;
    cudaGetSymbolAddress((void**)&x1h, g_x1h);
    cudaGetSymbolAddress((void**)&x1l, g_x1l);
    cudaGetSymbolAddress((void**)&x2t, g_x2t);
    cudaGetSymbolAddress((void**)&a0h, g_a0h);
    cudaGetSymbolAddress((void**)&a0l, g_a0l);
    cudaGetSymbolAddress((void**)&a1h, g_a1h);
    cudaGetSymbolAddress((void**)&a1l, g_a1l);
    cudaGetSymbolAddress((void**)&oB,  g_o);
    cudaGetSymbolAddress((void**)&wb0h, g_wb0h);
    cudaGetSymbolAddress((void**)&wb0l, g_wb0l);
    cudaGetSymbolAddress((void**)&wb1h, g_wb1h);
    cudaGetSymbolAddress((void**)&wb1l, g_wb1l);
    cudaGetSymbolAddress((void**)&wb2h, g_wb2h);
    cudaGetSymbolAddress((void**)&wb2l, g_wb2l);
    cudaGetSymbolAddress((void**)&wb3h, g_wb3h);
    cudaGetSymbolAddress((void**)&wb3l, g_wb3l);

    // SMEM: A halo hi/lo + B double buffer hi/lo, pitch ICA+8
    const int SMEM0 = 4 * 66 * (16 + 8) * 2 * 2  + 4 * 64 * (16 + 8) * 2;   //  37,632
    const int SMEM1 = 4 * 66 * (128 + 8) * 2 * 2 + 4 * 64 * (128 + 8) * 2;  // 213,248
    cudaFuncSetAttribute(conv_mma_kernel<16>,  cudaFuncAttributeMaxDynamicSharedMemorySize, SMEM0);
    cudaFuncSetAttribute(conv_mma_kernel<128>, cudaFuncAttributeMaxDynamicSharedMemorySize, SMEM1);

    // 1) split / passthrough
    {
        int n = Bn * 32 * Hh * Ww;
        prep_kernel<<<(n + 255) / 256, 256>>>(x, out);
    }
    // 2) weight tiling (hi/lo bf16, 64-oc tiles)
    {
        int n0 = 2 * 9 * 64 * 16;
        wprep_kernel<<<(n0 + 255) / 256, 256>>>(w0, wb0h, wb0l, HIDc, C1, n0);
        int n1 = 2 * 9 * 64 * 128;
        wprep_kernel<<<(n1 + 255) / 256, 256>>>(w1, wb1h, wb1l, HIDc, HIDc, n1);
        wprep_kernel<<<(n1 + 255) / 256, 256>>>(w2, wb2h, wb2l, HIDc, HIDc, n1);
        int n3 = 5 * 9 * 64 * 128;
        wprep_kernel<<<(n3 + 255) / 256, 256>>>(w3, wb3h, wb3l, OC4, HIDc, n3);
    }
    // 3) convs via mma.sync, B pipelined
    conv_mma_kernel<16><<<dim3(NPIX / 128, 2), 256, SMEM0>>>(
        x1h, x1l, wb0h, wb0l, b0, a0h, a0l, nullptr, HIDc);
    conv_mma_kernel<128><<<dim3(NPIX / 128, 2), 256, SMEM1>>>(
        a0h, a0l, wb1h, wb1l, b1, a1h, a1l, nullptr, HIDc);
    conv_mma_kernel<128><<<dim3(NPIX / 128, 2), 256, SMEM1>>>(
        a1h, a1l, wb2h, wb2l, b2, a0h, a0l, nullptr, HIDc);
    conv_mma_kernel<128><<<dim3(NPIX / 128, 5), 256, SMEM1>>>(
        a0h, a0l, wb3h, wb3l, b3, nullptr, nullptr, oB, OC4);
    // 4) expm (matvec Taylor) + assembly + log_det
    expm_kernel<<<NPIX / 16, 256>>>(oB, scale, shift_p, rescale, reshift, out);

    (void)in_sizes; (void)n_in; (void)out_size;
}

// round 7
// speedup vs baseline: 8.0145x; 1.1565x over previous
#include <cuda_runtime.h>
#include <cuda_fp16.h>
#include <math.h>
#include <stdint.h>

// Shapes (fixed)
#define Bn   16
#define Hh   64
#define Ww   64
#define C1   16
#define C2   16
#define HIDc 128
#define OC4  272          // C2*(C2+1)
#define NPIX (Bn*Hh*Ww)   // 65536

// ---------------------------------------------------------------------------
__device__ __forceinline__ uint32_t smem_u32(const void* p) {
    uint32_t a;
    asm("{ .reg .u64 t; cvta.to.shared.u64 t, %1; cvt.u32.u64 %0, t; }" : "=r"(a) : "l"(p));
    return a;
}

__device__ __forceinline__ void ldsm_x4(uint32_t (&r)[4], uint32_t addr) {
    asm volatile("ldmatrix.sync.aligned.m8n8.x4.shared.b16 {%0,%1,%2,%3}, [%4];"
        : "=r"(r[0]), "=r"(r[1]), "=r"(r[2]), "=r"(r[3]) : "r"(addr));
}

__device__ __forceinline__ void mma16816(float (&d)[4], const uint32_t (&a)[4],
                                         uint32_t b0, uint32_t b1) {
    asm volatile("mma.sync.aligned.m16n8k16.row.col.f32.f16.f16.f32 "
        "{%0,%1,%2,%3}, {%4,%5,%6,%7}, {%8,%9}, {%0,%1,%2,%3};"
        : "+f"(d[0]), "+f"(d[1]), "+f"(d[2]), "+f"(d[3])
        : "r"(a[0]), "r"(a[1]), "r"(a[2]), "r"(a[3]), "r"(b0), "r"(b1));
}

__device__ __forceinline__ void cp16(uint32_t dst, const void* src, bool pred) {
    asm volatile("cp.async.cg.shared.global [%0], [%1], 16, %2;"
        :: "r"(dst), "l"(src), "r"(pred ? 16u : 0u) : "memory");
}
#define CP_COMMIT() asm volatile("cp.async.commit_group;" ::: "memory")
#define CP_WAIT0()  asm volatile("cp.async.wait_group 0;" ::: "memory")
#define CP_WAIT1()  asm volatile("cp.async.wait_group 1;" ::: "memory")

__device__ __forceinline__ float eluf(float t) { return t > 0.0f ? t : expm1f(t); }

// ---------------- scratch (device globals) ----------------
__device__ __align__(16) __half g_x1h[NPIX * C1];
__device__ __align__(16) __half g_x1l[NPIX * C1];
__device__ __align__(16) float  g_x2t[NPIX * C2];
__device__ __align__(16) __half g_a0h[NPIX * HIDc];
__device__ __align__(16) __half g_a0l[NPIX * HIDc];
__device__ __align__(16) __half g_a1h[NPIX * HIDc];
__device__ __align__(16) __half g_a1l[NPIX * HIDc];
__device__ __align__(16) float  g_o  [(size_t)NPIX * OC4];
// pre-tiled weights: [tile64][tap][64 oc][ICA] fp16, hi/lo
__device__ __align__(16) __half g_wb0h[2 * 9 * 64 * 16];
__device__ __align__(16) __half g_wb0l[2 * 9 * 64 * 16];
__device__ __align__(16) __half g_wb1h[2 * 9 * 64 * 128];
__device__ __align__(16) __half g_wb1l[2 * 9 * 64 * 128];
__device__ __align__(16) __half g_wb2h[2 * 9 * 64 * 128];
__device__ __align__(16) __half g_wb2l[2 * 9 * 64 * 128];
__device__ __align__(16) __half g_wb3h[5 * 9 * 64 * 128];   // conv3: hi only used

// ---------------------------------------------------------------------------
// prep: NCHW -> NHWC split (x1 as fp16 hi/lo, x2 fp32), passthrough, zero logdet
// ---------------------------------------------------------------------------
__global__ void prep_kernel(const float* __restrict__ x, float* __restrict__ out)
{
    int idx = blockIdx.x * blockDim.x + threadIdx.x;
    if (idx < Bn) out[(size_t)Bn * 32 * Hh * Ww + idx] = 0.0f;
    if (idx >= Bn * 32 * Hh * Ww) return;
    int b = idx >> 17;
    int c = (idx >> 12) & 31;
    int p = idx & 4095;
    float v = x[idx];
    int pix = (b << 12) + p;
    if (c < C1) {
        out[idx] = v;
        __half h = __float2half_rn(v);
        g_x1h[pix * C1 + c] = h;
        g_x1l[pix * C1 + c] = __float2half_rn(v - __half2float(h));
    } else {
        g_x2t[pix * C2 + (c - C1)] = v;
    }
}

// ---------------------------------------------------------------------------
// wprep: w[OC][ICA][3][3] fp32 -> [tile64][tap][64][ICA] fp16 hi (+optional lo)
// ---------------------------------------------------------------------------
__global__ void wprep_kernel(const float* __restrict__ w,
                             __half* __restrict__ dh,
                             __half* __restrict__ dl,   // may be nullptr
                             int OC, int ICA, int total)
{
    int idx = blockIdx.x * blockDim.x + threadIdx.x;
    if (idx >= total) return;
    int k   = idx % ICA;
    int row = (idx / ICA) & 63;
    int tt  = idx / (ICA * 64);
    int tap  = tt % 9;
    int tile = tt / 9;
    int oc = tile * 64 + row;
    float v = (oc < OC) ? w[((size_t)oc * ICA + k) * 9 + tap] : 0.0f;
    __half h = __float2half_rn(v);
    dh[idx] = h;
    if (dl) dl[idx] = __float2half_rn(v - __half2float(h));
}

// ---------------------------------------------------------------------------
// B-tile stager: one tap (64 rows x ICA) into padded SMEM via cp.async
// ---------------------------------------------------------------------------
template<int ICA, bool LO>
__device__ __forceinline__ void stage_B(uint32_t dsth, uint32_t dstl,
                                        const __half* __restrict__ wh,
                                        const __half* __restrict__ wl,
                                        int tid)
{
    constexpr int VPA = ICA / 8;
    constexpr int PB  = (ICA + 8) * 2;
    const char* bh = (const char*)wh;
    const char* bl = (const char*)wl;
    for (int vi = tid; vi < 64 * VPA; vi += 256) {
        int row = vi / VPA, kv = vi % VPA;
        uint32_t d = row * PB + kv * 16;
        cp16(dsth + d, bh + vi * 16, true);
        if (LO) cp16(dstl + d, bl + vi * 16, true);
    }
}

// ---------------------------------------------------------------------------
// Implicit 3x3 conv via mma.sync; A halo resident, B double-buffered pipeline.
// CTA = 128 px (2 image rows) x 64 oc, 8 warps (4M x 2N), warp = 32px x 32oc.
// PROD=3: AhBh + AhBl + AlBh (fp32-like). PROD=2: AhB + AlB (B single fp16).
// ---------------------------------------------------------------------------
template<int ICA, int PROD>
__global__ __launch_bounds__(256, 1)
void conv_mma_kernel(const __half* __restrict__ in_hi,
                     const __half* __restrict__ in_lo,
                     const __half* __restrict__ wb_hi,
                     const __half* __restrict__ wb_lo,
                     const float* __restrict__ bias,
                     __half* __restrict__ out_hi,
                     __half* __restrict__ out_lo,
                     float* __restrict__ out_f32,
                     int OC_total)
{
    constexpr int PITCH = ICA + 8;
    constexpr int PB    = PITCH * 2;
    constexpr int AROWS = 4 * 66;
    constexpr int ATILE = AROWS * PB;
    constexpr int BTILE = 64 * PB;          // one buf, one precision
    constexpr int VPA   = ICA / 8;
    constexpr int KC    = ICA / 16;
    constexpr bool BLO  = (PROD == 3);

    extern __shared__ char smem[];
    const uint32_t sAh = smem_u32(smem);
    const uint32_t sAl = sAh + ATILE;
    const uint32_t sB  = sAl + ATILE;       // [buf][hi|lo]

    const int tid  = threadIdx.x;
    const int lane = tid & 31;
    const int warp = tid >> 5;
    const int warpN = warp & 1;             // 2 N tiles of 32 oc
    const int warpM = warp >> 1;            // 4 M tiles of 32 px

    const int pixbase = blockIdx.x * 128;
    const int b  = pixbase >> 12;
    const int y0 = (pixbase & 4095) >> 6;
    const int ocb = blockIdx.y;
    const bool active = (ocb * 64 + warpN * 32) < OC_total;
    const size_t wbase = (size_t)ocb * 9 * (64 * ICA);

    float acc[2][4][4];
    #pragma unroll
    for (int mt = 0; mt < 2; mt++)
        #pragma unroll
        for (int nt = 0; nt < 4; nt++)
            #pragma unroll
            for (int q = 0; q < 4; q++) acc[mt][nt][q] = 0.0f;

    // ---- prologue: A halo + B[0] (group0), B[1] (group1) ----
    for (int vi = tid; vi < AROWS * VPA; vi += 256) {
        int row = vi / VPA;
        int kv  = vi % VPA;
        int yy  = y0 + row / 66 - 1;
        int xx  = (row % 66) - 1;
        bool ok = (yy >= 0 && yy < Hh && xx >= 0 && xx < Ww);
        size_t src = ok ? (((size_t)((b << 12) + (yy << 6) + xx)) * ICA + kv * 8) : 0;
        uint32_t dst = row * PB + kv * 16;
        cp16(sAh + dst, in_hi + src, ok);
        cp16(sAl + dst, in_lo + src, ok);
    }
    stage_B<ICA, BLO>(sB, sB + BTILE, wb_hi + wbase, wb_lo + wbase, tid);
    CP_COMMIT();
    stage_B<ICA, BLO>(sB + 2 * BTILE, sB + 3 * BTILE,
                      wb_hi + wbase + 64 * ICA, wb_lo + wbase + 64 * ICA, tid);
    CP_COMMIT();
    CP_WAIT1();
    __syncthreads();

    // per-lane ldmatrix base offsets
    const uint32_t a_base = (uint32_t)(((warpM >> 1) + 1) * 66
                          + (warpM & 1) * 32 + (lane & 15) + 1) * PB
                          + (uint32_t)(lane & 16);
    const uint32_t b_base = (uint32_t)(warpN * 32 + (lane & 7) + ((lane & 16) >> 1)) * PB
                          + (uint32_t)((lane & 8) << 1);

    for (int tap = 0; tap < 9; tap++) {
        const uint32_t bufh = sB + (uint32_t)(tap & 1) * (2 * BTILE);
        const uint32_t bufl = bufh + BTILE;

        if (active) {
            const int dy = tap / 3 - 1, dx = tap % 3 - 1;
            const uint32_t tapoff = (uint32_t)((dy * 66 + dx) * PB);
            #pragma unroll
            for (int kc = 0; kc < KC; kc++) {
                const uint32_t k0b = kc * 32;
                uint32_t Ah[2][4], Al[2][4], Bh[2][4], Bl[2][4];
                #pragma unroll
                for (int mt = 0; mt < 2; mt++) {
                    uint32_t off = a_base + tapoff + k0b + (uint32_t)(mt * 16) * PB;
                    ldsm_x4(Ah[mt], sAh + off);
                    ldsm_x4(Al[mt], sAl + off);
                }
                #pragma unroll
                for (int p = 0; p < 2; p++) {
                    uint32_t off = b_base + k0b + (uint32_t)(p * 16) * PB;
                    ldsm_x4(Bh[p], bufh + off);
                    if (BLO) ldsm_x4(Bl[p], bufl + off);
                }
                #pragma unroll
                for (int mt = 0; mt < 2; mt++) {
                    #pragma unroll
                    for (int nt = 0; nt < 4; nt++) {
                        const int pr = nt >> 1, rr = (nt & 1) * 2;
                        mma16816(acc[mt][nt], Ah[mt], Bh[pr][rr], Bh[pr][rr + 1]);
                        if (BLO)
                            mma16816(acc[mt][nt], Ah[mt], Bl[pr][rr], Bl[pr][rr + 1]);
                        mma16816(acc[mt][nt], Al[mt], Bh[pr][rr], Bh[pr][rr + 1]);
                    }
                }
            }
        }
        __syncthreads();   // all warps done reading buf[tap&1]
        if (tap + 2 <= 8) {
            uint32_t nbh = sB + (uint32_t)(tap & 1) * (2 * BTILE);
            stage_B<ICA, BLO>(nbh, nbh + BTILE,
                              wb_hi + wbase + (size_t)(tap + 2) * 64 * ICA,
                              wb_lo + wbase + (size_t)(tap + 2) * 64 * ICA, tid);
            CP_COMMIT();
            CP_WAIT1();    // B[tap+1] complete (only B[tap+2] may pend)
        } else {
            CP_WAIT0();
        }
        __syncthreads();
    }

    // --- epilogue ---
    if (!active) return;
    #pragma unroll
    for (int mt = 0; mt < 2; mt++) {
        #pragma unroll
        for (int nt = 0; nt < 4; nt++) {
            const int cl = warpN * 32 + nt * 8 + (lane & 3) * 2;   // local oc (even)
            const int oc = ocb * 64 + cl;                          // global oc
            if (oc >= OC_total) continue;
            const float b0 = bias[oc], b1 = bias[oc + 1];
            const int r0 = pixbase + (warpM >> 1) * 64 + (warpM & 1) * 32
                         + mt * 16 + (lane >> 2);
            #pragma unroll
            for (int h = 0; h < 2; h++) {
                const int pix = r0 + h * 8;
                float v0 = acc[mt][nt][2 * h]     + b0;
                float v1 = acc[mt][nt][2 * h + 1] + b1;
                if (out_f32) {
                    float2 fv = make_float2(v0, v1);
                    *(float2*)(out_f32 + (size_t)pix * OC4 + oc) = fv;
                } else {
                    v0 = eluf(v0);
                    v1 = eluf(v1);
                    __half h0 = __float2half_rn(v0);
                    __half h1 = __float2half_rn(v1);
                    __half l0 = __float2half_rn(v0 - __half2float(h0));
                    __half l1 = __float2half_rn(v1 - __half2float(h1));
                    uint32_t hw = (uint32_t)__half_as_ushort(h0) | ((uint32_t)__half_as_ushort(h1) << 16);
                    uint32_t lw = (uint32_t)__half_as_ushort(l0) | ((uint32_t)__half_as_ushort(l1) << 16);
                    *(uint32_t*)(out_hi + (size_t)pix * 128 + oc) = hw;
                    *(uint32_t*)(out_lo + (size_t)pix * 128 + oc) = lw;
                }
            }
        }
    }
}

// ---------------------------------------------------------------------------
// expm kernel, MATVEC form: y2 = sum_k A^k x2 / k!, 18 matvecs per pixel.
// ---------------------------------------------------------------------------
__global__ __launch_bounds__(256)
void expm_kernel(const float* __restrict__ o,
                 const float* __restrict__ scale, const float* __restrict__ shift_p,
                 const float* __restrict__ rescale, const float* __restrict__ reshift,
                 float* __restrict__ out)
{
    __shared__ float sT[16][20];
    __shared__ float sY[16][17];
    __shared__ float sTr[8];

    const int tid  = threadIdx.x;
    const int lane = tid & 31;
    const int warp = tid >> 5;
    const int half = lane >> 4;
    const int r    = lane & 15;
    const int pixB = warp * 2 + half;

    const int pix_base = blockIdx.x * 16;
    const int b  = pix_base >> 12;
    const int p  = pix_base & 4095;
    const int y  = p >> 6;
    const int x0 = p & 63;
    const int pix = pix_base + pixB;

    const float sc = scale[0], sp = shift_p[0], rs = rescale[0], rf = reshift[0];
    const float* op = o + (size_t)pix * OC4;

    float arow[16];
    #pragma unroll
    for (int j = 0; j < 16; j++) {
        float v = op[(j + 1) * 16 + r];
        arow[j] = rs * tanhf(sc * v + sp) + rf;
    }
    float tr = arow[r];

    const float x2v = g_x2t[(size_t)pix * 16 + r];
    sT[pixB][r] = x2v;
    float yacc = x2v;
    __syncwarp();

    #pragma unroll
    for (int k = 1; k <= 18; k++) {
        float s = 0.0f;
        #pragma unroll
        for (int j = 0; j < 16; j++) s += arow[j] * sT[pixB][j];
        s *= (1.0f / (float)k);
        __syncwarp();
        sT[pixB][r] = s;
        __syncwarp();
        yacc += s;
    }

    sY[pixB][r] = yacc + op[r];

    #pragma unroll
    for (int off = 16; off > 0; off >>= 1) tr += __shfl_down_sync(0xffffffffu, tr, off);
    if (lane == 0) sTr[warp] = tr;
    __syncthreads();
    if (tid == 0) {
        float s = 0.0f;
        #pragma unroll
        for (int w2 = 0; w2 < 8; w2++) s += sTr[w2];
        atomicAdd(out + (size_t)Bn * 32 * Hh * Ww + b, s);
    }

    const int c  = tid >> 4;
    const int p2 = tid & 15;
    out[((size_t)(b * 32 + 16 + c)) * (Hh * Ww) + y * Ww + x0 + p2] = sY[p2][c];
}

// ---------------------------------------------------------------------------
extern "C" void kernel_launch(void* const* d_in, const int* in_sizes, int n_in,
                              void* d_out, int out_size)
{
    const float* x       = (const float*)d_in[0];
    const float* scale   = (const float*)d_in[1];
    const float* shift_p = (const float*)d_in[2];
    const float* rescale = (const float*)d_in[3];
    const float* reshift = (const float*)d_in[4];
    const float* w0 = (const float*)d_in[5];
    const float* b0 = (const float*)d_in[6];
    const float* w1 = (const float*)d_in[7];
    const float* b1 = (const float*)d_in[8];
    const float* w2 = (const float*)d_in[9];
    const float* b2 = (const float*)d_in[10];
    const float* w3 = (const float*)d_in[11];
    const float* b3 = (const float*)d_in[12];
    float* out = (float*)d_out;

    __half *x1h, *x1l, *a0h, *a0l, *a1h, *a1l;
    __half *wb0h, *wb0l, *wb1h, *wb1l, *wb2h, *wb2l, *wb3h;
    float *x2t, *oB;
    cudaGetSymbolAddress((void**)&x1h, g_x1h);
    cudaGetSymbolAddress((void**)&x1l, g_x1l);
    cudaGetSymbolAddress((void**)&x2t, g_x2t);
    cudaGetSymbolAddress((void**)&a0h, g_a0h);
    cudaGetSymbolAddress((void**)&a0l, g_a0l);
    cudaGetSymbolAddress((void**)&a1h, g_a1h);
    cudaGetSymbolAddress((void**)&a1l, g_a1l);
    cudaGetSymbolAddress((void**)&oB,  g_o);
    cudaGetSymbolAddress((void**)&wb0h, g_wb0h);
    cudaGetSymbolAddress((void**)&wb0l, g_wb0l);
    cudaGetSymbolAddress((void**)&wb1h, g_wb1h);
    cudaGetSymbolAddress((void**)&wb1l, g_wb1l);
    cudaGetSymbolAddress((void**)&wb2h, g_wb2h);
    cudaGetSymbolAddress((void**)&wb2l, g_wb2l);
    cudaGetSymbolAddress((void**)&wb3h, g_wb3h);

    // SMEM: A halo hi/lo + B double buffer hi/lo, pitch ICA+8
    const int SMEM0 = 4 * 66 * (16 + 8) * 2 * 2  + 4 * 64 * (16 + 8) * 2;   //  37,632
    const int SMEM1 = 4 * 66 * (128 + 8) * 2 * 2 + 4 * 64 * (128 + 8) * 2;  // 213,248
    cudaFuncSetAttribute(conv_mma_kernel<16, 3>,  cudaFuncAttributeMaxDynamicSharedMemorySize, SMEM0);
    cudaFuncSetAttribute(conv_mma_kernel<128, 3>, cudaFuncAttributeMaxDynamicSharedMemorySize, SMEM1);
    cudaFuncSetAttribute(conv_mma_kernel<128, 2>, cudaFuncAttributeMaxDynamicSharedMemorySize, SMEM1);

    // 1) split / passthrough
    {
        int n = Bn * 32 * Hh * Ww;
        prep_kernel<<<(n + 255) / 256, 256>>>(x, out);
    }
    // 2) weight tiling (fp16, 64-oc tiles)
    {
        int n0 = 2 * 9 * 64 * 16;
        wprep_kernel<<<(n0 + 255) / 256, 256>>>(w0, wb0h, wb0l, HIDc, C1, n0);
        int n1 = 2 * 9 * 64 * 128;
        wprep_kernel<<<(n1 + 255) / 256, 256>>>(w1, wb1h, wb1l, HIDc, HIDc, n1);
        wprep_kernel<<<(n1 + 255) / 256, 256>>>(w2, wb2h, wb2l, HIDc, HIDc, n1);
        int n3 = 5 * 9 * 64 * 128;
        wprep_kernel<<<(n3 + 255) / 256, 256>>>(w3, wb3h, (__half*)nullptr, OC4, HIDc, n3);
    }
    // 3) convs via mma.sync: convs 0-2 = 3-product fp16, conv3 = 2-product
    conv_mma_kernel<16, 3><<<dim3(NPIX / 128, 2), 256, SMEM0>>>(
        x1h, x1l, wb0h, wb0l, b0, a0h, a0l, nullptr, HIDc);
    conv_mma_kernel<128, 3><<<dim3(NPIX / 128, 2), 256, SMEM1>>>(
        a0h, a0l, wb1h, wb1l, b1, a1h, a1l, nullptr, HIDc);
    conv_mma_kernel<128, 3><<<dim3(NPIX / 128, 2), 256, SMEM1>>>(
        a1h, a1l, wb2h, wb2l, b2, a0h, a0l, nullptr, HIDc);
    conv_mma_kernel<128, 2><<<dim3(NPIX / 128, 5), 256, SMEM1>>>(
        a0h, a0l, wb3h, wb3h, b3, nullptr, nullptr, oB, OC4);
    // 4) expm (matvec Taylor) + assembly + log_det
    expm_kernel<<<NPIX / 16, 256>>>(oB, scale, shift_p, rescale, reshift, out);

    (void)in_sizes; (void)n_in; (void)out_size;
}

// round 8
// speedup vs baseline: 9.3188x; 1.1627x over previous
#include <cuda_runtime.h>
#include <cuda_fp16.h>
#include <math.h>
#include <stdint.h>

// Shapes (fixed)
#define Bn   16
#define Hh   64
#define Ww   64
#define C1   16
#define C2   16
#define HIDc 128
#define OC4  272          // C2*(C2+1)
#define NPIX (Bn*Hh*Ww)   // 65536

// ---------------------------------------------------------------------------
__device__ __forceinline__ uint32_t smem_u32(const void* p) {
    uint32_t a;
    asm("{ .reg .u64 t; cvta.to.shared.u64 t, %1; cvt.u32.u64 %0, t; }" : "=r"(a) : "l"(p));
    return a;
}

__device__ __forceinline__ void ldsm_x4(uint32_t (&r)[4], uint32_t addr) {
    asm volatile("ldmatrix.sync.aligned.m8n8.x4.shared.b16 {%0,%1,%2,%3}, [%4];"
        : "=r"(r[0]), "=r"(r[1]), "=r"(r[2]), "=r"(r[3]) : "r"(addr));
}

__device__ __forceinline__ void mma16816(float (&d)[4], const uint32_t (&a)[4],
                                         uint32_t b0, uint32_t b1) {
    asm volatile("mma.sync.aligned.m16n8k16.row.col.f32.f16.f16.f32 "
        "{%0,%1,%2,%3}, {%4,%5,%6,%7}, {%8,%9}, {%0,%1,%2,%3};"
        : "+f"(d[0]), "+f"(d[1]), "+f"(d[2]), "+f"(d[3])
        : "r"(a[0]), "r"(a[1]), "r"(a[2]), "r"(a[3]), "r"(b0), "r"(b1));
}

__device__ __forceinline__ void cp16(uint32_t dst, const void* src, bool pred) {
    asm volatile("cp.async.cg.shared.global [%0], [%1], 16, %2;"
        :: "r"(dst), "l"(src), "r"(pred ? 16u : 0u) : "memory");
}
#define CP_COMMIT() asm volatile("cp.async.commit_group;" ::: "memory")
#define CP_WAIT0()  asm volatile("cp.async.wait_group 0;" ::: "memory")
#define CP_WAIT1()  asm volatile("cp.async.wait_group 1;" ::: "memory")

__device__ __forceinline__ float eluf(float t) { return t > 0.0f ? t : expm1f(t); }

// ---------------- scratch (device globals) ----------------
__device__ __align__(16) __half g_x1h[NPIX * C1];
__device__ __align__(16) __half g_x1l[NPIX * C1];
__device__ __align__(16) float  g_x2t[NPIX * C2];
__device__ __align__(16) __half g_a0h[NPIX * HIDc];
__device__ __align__(16) __half g_a0l[NPIX * HIDc];
__device__ __align__(16) __half g_a1h[NPIX * HIDc];
__device__ __align__(16) __half g_a1l[NPIX * HIDc];
__device__ __align__(16) float  g_o  [(size_t)NPIX * OC4];
// pre-tiled weights: [tile64][tap][64 oc][ICA] fp16 (lo only where 3-product)
__device__ __align__(16) __half g_wb0h[2 * 9 * 64 * 16];
__device__ __align__(16) __half g_wb0l[2 * 9 * 64 * 16];
__device__ __align__(16) __half g_wb1h[2 * 9 * 64 * 128];
__device__ __align__(16) __half g_wb2h[2 * 9 * 64 * 128];
__device__ __align__(16) __half g_wb3h[5 * 9 * 64 * 128];

// ---------------------------------------------------------------------------
// prep: NCHW -> NHWC split (x1 as fp16 hi/lo, x2 fp32), passthrough, zero logdet
// ---------------------------------------------------------------------------
__global__ void prep_kernel(const float* __restrict__ x, float* __restrict__ out)
{
    int idx = blockIdx.x * blockDim.x + threadIdx.x;
    if (idx < Bn) out[(size_t)Bn * 32 * Hh * Ww + idx] = 0.0f;
    if (idx >= Bn * 32 * Hh * Ww) return;
    int b = idx >> 17;
    int c = (idx >> 12) & 31;
    int p = idx & 4095;
    float v = x[idx];
    int pix = (b << 12) + p;
    if (c < C1) {
        out[idx] = v;
        __half h = __float2half_rn(v);
        g_x1h[pix * C1 + c] = h;
        g_x1l[pix * C1 + c] = __float2half_rn(v - __half2float(h));
    } else {
        g_x2t[pix * C2 + (c - C1)] = v;
    }
}

// ---------------------------------------------------------------------------
// wprep: w[OC][ICA][3][3] fp32 -> [tile64][tap][64][ICA] fp16 hi (+optional lo)
// ---------------------------------------------------------------------------
__global__ void wprep_kernel(const float* __restrict__ w,
                             __half* __restrict__ dh,
                             __half* __restrict__ dl,   // may be nullptr
                             int OC, int ICA, int total)
{
    int idx = blockIdx.x * blockDim.x + threadIdx.x;
    if (idx >= total) return;
    int k   = idx % ICA;
    int row = (idx / ICA) & 63;
    int tt  = idx / (ICA * 64);
    int tap  = tt % 9;
    int tile = tt / 9;
    int oc = tile * 64 + row;
    float v = (oc < OC) ? w[((size_t)oc * ICA + k) * 9 + tap] : 0.0f;
    __half h = __float2half_rn(v);
    dh[idx] = h;
    if (dl) dl[idx] = __float2half_rn(v - __half2float(h));
}

// ---------------------------------------------------------------------------
// B-tile stager: one tap (64 rows x ICA) into padded SMEM via cp.async
// ---------------------------------------------------------------------------
template<int ICA, bool LO>
__device__ __forceinline__ void stage_B(uint32_t dsth, uint32_t dstl,
                                        const __half* __restrict__ wh,
                                        const __half* __restrict__ wl,
                                        int tid)
{
    constexpr int VPA = ICA / 8;
    constexpr int PB  = (ICA + 8) * 2;
    const char* bh = (const char*)wh;
    const char* bl = (const char*)wl;
    for (int vi = tid; vi < 64 * VPA; vi += 256) {
        int row = vi / VPA, kv = vi % VPA;
        uint32_t d = row * PB + kv * 16;
        cp16(dsth + d, bh + vi * 16, true);
        if (LO) cp16(dstl + d, bl + vi * 16, true);
    }
}

// ---------------------------------------------------------------------------
// Implicit 3x3 conv via mma.sync; A halo resident, B double-buffered pipeline.
// CTA = 128 px (2 image rows) x 64 oc, 8 warps (4M x 2N), warp = 32px x 32oc.
// PROD=3: AhBh + AhBl + AlBh. PROD=2: AhB + AlB (B single fp16).
// ---------------------------------------------------------------------------
template<int ICA, int PROD>
__global__ __launch_bounds__(256, 1)
void conv_mma_kernel(const __half* __restrict__ in_hi,
                     const __half* __restrict__ in_lo,
                     const __half* __restrict__ wb_hi,
                     const __half* __restrict__ wb_lo,
                     const float* __restrict__ bias,
                     __half* __restrict__ out_hi,
                     __half* __restrict__ out_lo,
                     float* __restrict__ out_f32,
                     int OC_total)
{
    constexpr int PITCH = ICA + 8;
    constexpr int PB    = PITCH * 2;
    constexpr int AROWS = 4 * 66;
    constexpr int ATILE = AROWS * PB;
    constexpr int BTILE = 64 * PB;          // one buf, one precision
    constexpr int VPA   = ICA / 8;
    constexpr int KC    = ICA / 16;
    constexpr bool BLO  = (PROD == 3);

    extern __shared__ char smem[];
    const uint32_t sAh = smem_u32(smem);
    const uint32_t sAl = sAh + ATILE;
    const uint32_t sB  = sAl + ATILE;       // [buf][hi|lo]
    constexpr int BSTRIDE = BLO ? 2 : 1;    // BTILEs per buffer

    const int tid  = threadIdx.x;
    const int lane = tid & 31;
    const int warp = tid >> 5;
    const int warpN = warp & 1;             // 2 N tiles of 32 oc
    const int warpM = warp >> 1;            // 4 M tiles of 32 px

    const int pixbase = blockIdx.x * 128;
    const int b  = pixbase >> 12;
    const int y0 = (pixbase & 4095) >> 6;
    const int ocb = blockIdx.y;
    const bool active = (ocb * 64 + warpN * 32) < OC_total;
    const size_t wbase = (size_t)ocb * 9 * (64 * ICA);

    float acc[2][4][4];
    #pragma unroll
    for (int mt = 0; mt < 2; mt++)
        #pragma unroll
        for (int nt = 0; nt < 4; nt++)
            #pragma unroll
            for (int q = 0; q < 4; q++) acc[mt][nt][q] = 0.0f;

    // ---- prologue: A halo + B[0] (group0), B[1] (group1) ----
    for (int vi = tid; vi < AROWS * VPA; vi += 256) {
        int row = vi / VPA;
        int kv  = vi % VPA;
        int yy  = y0 + row / 66 - 1;
        int xx  = (row % 66) - 1;
        bool ok = (yy >= 0 && yy < Hh && xx >= 0 && xx < Ww);
        size_t src = ok ? (((size_t)((b << 12) + (yy << 6) + xx)) * ICA + kv * 8) : 0;
        uint32_t dst = row * PB + kv * 16;
        cp16(sAh + dst, in_hi + src, ok);
        cp16(sAl + dst, in_lo + src, ok);
    }
    stage_B<ICA, BLO>(sB, sB + BTILE, wb_hi + wbase, wb_lo + wbase, tid);
    CP_COMMIT();
    stage_B<ICA, BLO>(sB + BSTRIDE * BTILE, sB + (BSTRIDE + 1) * BTILE,
                      wb_hi + wbase + 64 * ICA, wb_lo + wbase + 64 * ICA, tid);
    CP_COMMIT();
    CP_WAIT1();
    __syncthreads();

    // per-lane ldmatrix base offsets
    const uint32_t a_base = (uint32_t)(((warpM >> 1) + 1) * 66
                          + (warpM & 1) * 32 + (lane & 15) + 1) * PB
                          + (uint32_t)(lane & 16);
    const uint32_t b_base = (uint32_t)(warpN * 32 + (lane & 7) + ((lane & 16) >> 1)) * PB
                          + (uint32_t)((lane & 8) << 1);

    for (int tap = 0; tap < 9; tap++) {
        const uint32_t bufh = sB + (uint32_t)(tap & 1) * (BSTRIDE * BTILE);
        const uint32_t bufl = bufh + BTILE;

        if (active) {
            const int dy = tap / 3 - 1, dx = tap % 3 - 1;
            const uint32_t tapoff = (uint32_t)((dy * 66 + dx) * PB);
            #pragma unroll
            for (int kc = 0; kc < KC; kc++) {
                const uint32_t k0b = kc * 32;
                uint32_t Ah[2][4], Al[2][4], Bh[2][4], Bl[2][4];
                #pragma unroll
                for (int mt = 0; mt < 2; mt++) {
                    uint32_t off = a_base + tapoff + k0b + (uint32_t)(mt * 16) * PB;
                    ldsm_x4(Ah[mt], sAh + off);
                    ldsm_x4(Al[mt], sAl + off);
                }
                #pragma unroll
                for (int p = 0; p < 2; p++) {
                    uint32_t off = b_base + k0b + (uint32_t)(p * 16) * PB;
                    ldsm_x4(Bh[p], bufh + off);
                    if (BLO) ldsm_x4(Bl[p], bufl + off);
                }
                #pragma unroll
                for (int mt = 0; mt < 2; mt++) {
                    #pragma unroll
                    for (int nt = 0; nt < 4; nt++) {
                        const int pr = nt >> 1, rr = (nt & 1) * 2;
                        mma16816(acc[mt][nt], Ah[mt], Bh[pr][rr], Bh[pr][rr + 1]);
                        if (BLO)
                            mma16816(acc[mt][nt], Ah[mt], Bl[pr][rr], Bl[pr][rr + 1]);
                        mma16816(acc[mt][nt], Al[mt], Bh[pr][rr], Bh[pr][rr + 1]);
                    }
                }
            }
        }
        __syncthreads();   // all warps done reading buf[tap&1]
        if (tap + 2 <= 8) {
            uint32_t nbh = sB + (uint32_t)(tap & 1) * (BSTRIDE * BTILE);
            stage_B<ICA, BLO>(nbh, nbh + BTILE,
                              wb_hi + wbase + (size_t)(tap + 2) * 64 * ICA,
                              wb_lo + wbase + (size_t)(tap + 2) * 64 * ICA, tid);
            CP_COMMIT();
            CP_WAIT1();    // B[tap+1] complete (only B[tap+2] may pend)
        } else {
            CP_WAIT0();
        }
        __syncthreads();
    }

    // --- epilogue ---
    if (!active) return;
    #pragma unroll
    for (int mt = 0; mt < 2; mt++) {
        #pragma unroll
        for (int nt = 0; nt < 4; nt++) {
            const int cl = warpN * 32 + nt * 8 + (lane & 3) * 2;   // local oc (even)
            const int oc = ocb * 64 + cl;                          // global oc
            if (oc >= OC_total) continue;
            const float b0 = bias[oc], b1 = bias[oc + 1];
            const int r0 = pixbase + (warpM >> 1) * 64 + (warpM & 1) * 32
                         + mt * 16 + (lane >> 2);
            #pragma unroll
            for (int h = 0; h < 2; h++) {
                const int pix = r0 + h * 8;
                float v0 = acc[mt][nt][2 * h]     + b0;
                float v1 = acc[mt][nt][2 * h + 1] + b1;
                if (out_f32) {
                    float2 fv = make_float2(v0, v1);
                    *(float2*)(out_f32 + (size_t)pix * OC4 + oc) = fv;
                } else {
                    v0 = eluf(v0);
                    v1 = eluf(v1);
                    __half h0 = __float2half_rn(v0);
                    __half h1 = __float2half_rn(v1);
                    __half l0 = __float2half_rn(v0 - __half2float(h0));
                    __half l1 = __float2half_rn(v1 - __half2float(h1));
                    uint32_t hw = (uint32_t)__half_as_ushort(h0) | ((uint32_t)__half_as_ushort(h1) << 16);
                    uint32_t lw = (uint32_t)__half_as_ushort(l0) | ((uint32_t)__half_as_ushort(l1) << 16);
                    *(uint32_t*)(out_hi + (size_t)pix * 128 + oc) = hw;
                    *(uint32_t*)(out_lo + (size_t)pix * 128 + oc) = lw;
                }
            }
        }
    }
}

// ---------------------------------------------------------------------------
// expm kernel, MATVEC form: y2 = sum_k A^k x2 / k!, 18 matvecs per pixel.
// ---------------------------------------------------------------------------
__global__ __launch_bounds__(256)
void expm_kernel(const float* __restrict__ o,
                 const float* __restrict__ scale, const float* __restrict__ shift_p,
                 const float* __restrict__ rescale, const float* __restrict__ reshift,
                 float* __restrict__ out)
{
    __shared__ float sT[16][20];
    __shared__ float sY[16][17];
    __shared__ float sTr[8];

    const int tid  = threadIdx.x;
    const int lane = tid & 31;
    const int warp = tid >> 5;
    const int half = lane >> 4;
    const int r    = lane & 15;
    const int pixB = warp * 2 + half;

    const int pix_base = blockIdx.x * 16;
    const int b  = pix_base >> 12;
    const int p  = pix_base & 4095;
    const int y  = p >> 6;
    const int x0 = p & 63;
    const int pix = pix_base + pixB;

    const float sc = scale[0], sp = shift_p[0], rs = rescale[0], rf = reshift[0];
    const float* op = o + (size_t)pix * OC4;

    float arow[16];
    #pragma unroll
    for (int j = 0; j < 16; j++) {
        float v = op[(j + 1) * 16 + r];
        arow[j] = rs * tanhf(sc * v + sp) + rf;
    }
    float tr = arow[r];

    const float x2v = g_x2t[(size_t)pix * 16 + r];
    sT[pixB][r] = x2v;
    float yacc = x2v;
    __syncwarp();

    #pragma unroll
    for (int k = 1; k <= 18; k++) {
        float s = 0.0f;
        #pragma unroll
        for (int j = 0; j < 16; j++) s += arow[j] * sT[pixB][j];
        s *= (1.0f / (float)k);
        __syncwarp();
        sT[pixB][r] = s;
        __syncwarp();
        yacc += s;
    }

    sY[pixB][r] = yacc + op[r];

    #pragma unroll
    for (int off = 16; off > 0; off >>= 1) tr += __shfl_down_sync(0xffffffffu, tr, off);
    if (lane == 0) sTr[warp] = tr;
    __syncthreads();
    if (tid == 0) {
        float s = 0.0f;
        #pragma unroll
        for (int w2 = 0; w2 < 8; w2++) s += sTr[w2];
        atomicAdd(out + (size_t)Bn * 32 * Hh * Ww + b, s);
    }

    const int c  = tid >> 4;
    const int p2 = tid & 15;
    out[((size_t)(b * 32 + 16 + c)) * (Hh * Ww) + y * Ww + x0 + p2] = sY[p2][c];
}

// ---------------------------------------------------------------------------
extern "C" void kernel_launch(void* const* d_in, const int* in_sizes, int n_in,
                              void* d_out, int out_size)
{
    const float* x       = (const float*)d_in[0];
    const float* scale   = (const float*)d_in[1];
    const float* shift_p = (const float*)d_in[2];
    const float* rescale = (const float*)d_in[3];
    const float* reshift = (const float*)d_in[4];
    const float* w0 = (const float*)d_in[5];
    const float* b0 = (const float*)d_in[6];
    const float* w1 = (const float*)d_in[7];
    const float* b1 = (const float*)d_in[8];
    const float* w2 = (const float*)d_in[9];
    const float* b2 = (const float*)d_in[10];
    const float* w3 = (const float*)d_in[11];
    const float* b3 = (const float*)d_in[12];
    float* out = (float*)d_out;

    __half *x1h, *x1l, *a0h, *a0l, *a1h, *a1l;
    __half *wb0h, *wb0l, *wb1h, *wb2h, *wb3h;
    float *x2t, *oB;
    cudaGetSymbolAddress((void**)&x1h, g_x1h);
    cudaGetSymbolAddress((void**)&x1l, g_x1l);
    cudaGetSymbolAddress((void**)&x2t, g_x2t);
    cudaGetSymbolAddress((void**)&a0h, g_a0h);
    cudaGetSymbolAddress((void**)&a0l, g_a0l);
    cudaGetSymbolAddress((void**)&a1h, g_a1h);
    cudaGetSymbolAddress((void**)&a1l, g_a1l);
    cudaGetSymbolAddress((void**)&oB,  g_o);
    cudaGetSymbolAddress((void**)&wb0h, g_wb0h);
    cudaGetSymbolAddress((void**)&wb0l, g_wb0l);
    cudaGetSymbolAddress((void**)&wb1h, g_wb1h);
    cudaGetSymbolAddress((void**)&wb2h, g_wb2h);
    cudaGetSymbolAddress((void**)&wb3h, g_wb3h);

    // SMEM: A halo hi/lo + B double buffer (hi/lo only for PROD=3)
    const int SMEM0_3 = 4 * 66 * (16 + 8) * 2 * 2  + 4 * 64 * (16 + 8) * 2;   //  37,632
    const int SMEM1_3 = 4 * 66 * (128 + 8) * 2 * 2 + 4 * 64 * (128 + 8) * 2;  // 213,248
    const int SMEM1_2 = 4 * 66 * (128 + 8) * 2 * 2 + 2 * 64 * (128 + 8) * 2;  // 178,432
    cudaFuncSetAttribute(conv_mma_kernel<16, 3>,  cudaFuncAttributeMaxDynamicSharedMemorySize, SMEM0_3);
    cudaFuncSetAttribute(conv_mma_kernel<128, 2>, cudaFuncAttributeMaxDynamicSharedMemorySize, SMEM1_2);

    // 1) split / passthrough
    {
        int n = Bn * 32 * Hh * Ww;
        prep_kernel<<<(n + 255) / 256, 256>>>(x, out);
    }
    // 2) weight tiling (fp16, 64-oc tiles; lo only for conv0)
    {
        int n0 = 2 * 9 * 64 * 16;
        wprep_kernel<<<(n0 + 255) / 256, 256>>>(w0, wb0h, wb0l, HIDc, C1, n0);
        int n1 = 2 * 9 * 64 * 128;
        wprep_kernel<<<(n1 + 255) / 256, 256>>>(w1, wb1h, (__half*)nullptr, HIDc, HIDc, n1);
        wprep_kernel<<<(n1 + 255) / 256, 256>>>(w2, wb2h, (__half*)nullptr, HIDc, HIDc, n1);
        int n3 = 5 * 9 * 64 * 128;
        wprep_kernel<<<(n3 + 255) / 256, 256>>>(w3, wb3h, (__half*)nullptr, OC4, HIDc, n3);
    }
    // 3) convs: conv0 3-product, convs 1-3 2-product (A hi/lo x B fp16)
    conv_mma_kernel<16, 3><<<dim3(NPIX / 128, 2), 256, SMEM0_3>>>(
        x1h, x1l, wb0h, wb0l, b0, a0h, a0l, nullptr, HIDc);
    conv_mma_kernel<128, 2><<<dim3(NPIX / 128, 2), 256, SMEM1_2>>>(
        a0h, a0l, wb1h, wb1h, b1, a1h, a1l, nullptr, HIDc);
    conv_mma_kernel<128, 2><<<dim3(NPIX / 128, 2), 256, SMEM1_2>>>(
        a1h, a1l, wb2h, wb2h, b2, a0h, a0l, nullptr, HIDc);
    conv_mma_kernel<128, 2><<<dim3(NPIX / 128, 5), 256, SMEM1_2>>>(
        a0h, a0l, wb3h, wb3h, b3, nullptr, nullptr, oB, OC4);
    // 4) expm (matvec Taylor) + assembly + log_det
    expm_kernel<<<NPIX / 16, 256>>>(oB, scale, shift_p, rescale, reshift, out);

    (void)in_sizes; (void)n_in; (void)out_size;
}

// round 9
// speedup vs baseline: 15.7805x; 1.6934x over previous
#include <cuda_runtime.h>
#include <cuda_fp16.h>
#include <math.h>
#include <stdint.h>

// Shapes (fixed)
#define Bn   16
#define Hh   64
#define Ww   64
#define C1   16
#define C2   16
#define HIDc 128
#define OC4  272          // C2*(C2+1)
#define NPIX (Bn*Hh*Ww)   // 65536

// ---------------------------------------------------------------------------
__device__ __forceinline__ uint32_t smem_u32(const void* p) {
    uint32_t a;
    asm("{ .reg .u64 t; cvta.to.shared.u64 t, %1; cvt.u32.u64 %0, t; }" : "=r"(a) : "l"(p));
    return a;
}

__device__ __forceinline__ void ldsm_x4(uint32_t (&r)[4], uint32_t addr) {
    asm volatile("ldmatrix.sync.aligned.m8n8.x4.shared.b16 {%0,%1,%2,%3}, [%4];"
        : "=r"(r[0]), "=r"(r[1]), "=r"(r[2]), "=r"(r[3]) : "r"(addr));
}

__device__ __forceinline__ void mma16816(float (&d)[4], const uint32_t (&a)[4],
                                         uint32_t b0, uint32_t b1) {
    asm volatile("mma.sync.aligned.m16n8k16.row.col.f32.f16.f16.f32 "
        "{%0,%1,%2,%3}, {%4,%5,%6,%7}, {%8,%9}, {%0,%1,%2,%3};"
        : "+f"(d[0]), "+f"(d[1]), "+f"(d[2]), "+f"(d[3])
        : "r"(a[0]), "r"(a[1]), "r"(a[2]), "r"(a[3]), "r"(b0), "r"(b1));
}

__device__ __forceinline__ void cp16(uint32_t dst, const void* src, bool pred) {
    asm volatile("cp.async.cg.shared.global [%0], [%1], 16, %2;"
        :: "r"(dst), "l"(src), "r"(pred ? 16u : 0u) : "memory");
}
#define CP_COMMIT() asm volatile("cp.async.commit_group;" ::: "memory")
#define CP_WAIT0()  asm volatile("cp.async.wait_group 0;" ::: "memory")
#define CP_WAIT1()  asm volatile("cp.async.wait_group 1;" ::: "memory")

__device__ __forceinline__ float eluf(float t) { return t > 0.0f ? t : expm1f(t); }

// ---------------- scratch (device globals) ----------------
__device__ __align__(16) __half g_x1h[NPIX * C1];
__device__ __align__(16) __half g_x1l[NPIX * C1];
__device__ __align__(16) float  g_x2t[NPIX * C2];
__device__ __align__(16) __half g_a0[NPIX * HIDc];
__device__ __align__(16) __half g_a1[NPIX * HIDc];
__device__ __align__(16) float  g_o [(size_t)NPIX * OC4];
// pre-tiled weights: [tile64][tap][64 oc][ICA] fp16 (lo only for conv0)
__device__ __align__(16) __half g_wb0h[2 * 9 * 64 * 16];
__device__ __align__(16) __half g_wb0l[2 * 9 * 64 * 16];
__device__ __align__(16) __half g_wb1h[2 * 9 * 64 * 128];
__device__ __align__(16) __half g_wb2h[2 * 9 * 64 * 128];
__device__ __align__(16) __half g_wb3h[5 * 9 * 64 * 128];

// ---------------------------------------------------------------------------
// prep: NCHW -> NHWC split (x1 as fp16 hi/lo, x2 fp32), passthrough, zero logdet
// ---------------------------------------------------------------------------
__global__ void prep_kernel(const float* __restrict__ x, float* __restrict__ out)
{
    int idx = blockIdx.x * blockDim.x + threadIdx.x;
    if (idx < Bn) out[(size_t)Bn * 32 * Hh * Ww + idx] = 0.0f;
    if (idx >= Bn * 32 * Hh * Ww) return;
    int b = idx >> 17;
    int c = (idx >> 12) & 31;
    int p = idx & 4095;
    float v = x[idx];
    int pix = (b << 12) + p;
    if (c < C1) {
        out[idx] = v;
        __half h = __float2half_rn(v);
        g_x1h[pix * C1 + c] = h;
        g_x1l[pix * C1 + c] = __float2half_rn(v - __half2float(h));
    } else {
        g_x2t[pix * C2 + (c - C1)] = v;
    }
}

// ---------------------------------------------------------------------------
// wprep: w[OC][ICA][3][3] fp32 -> [tile64][tap][64][ICA] fp16 hi (+optional lo)
// ---------------------------------------------------------------------------
__global__ void wprep_kernel(const float* __restrict__ w,
                             __half* __restrict__ dh,
                             __half* __restrict__ dl,   // may be nullptr
                             int OC, int ICA, int total)
{
    int idx = blockIdx.x * blockDim.x + threadIdx.x;
    if (idx >= total) return;
    int k   = idx % ICA;
    int row = (idx / ICA) & 63;
    int tt  = idx / (ICA * 64);
    int tap  = tt % 9;
    int tile = tt / 9;
    int oc = tile * 64 + row;
    float v = (oc < OC) ? w[((size_t)oc * ICA + k) * 9 + tap] : 0.0f;
    __half h = __float2half_rn(v);
    dh[idx] = h;
    if (dl) dl[idx] = __float2half_rn(v - __half2float(h));
}

// ---------------------------------------------------------------------------
// B-tile stager: one tap (64 rows x ICA) into padded SMEM via cp.async
// ---------------------------------------------------------------------------
template<int ICA, bool LO>
__device__ __forceinline__ void stage_B(uint32_t dsth, uint32_t dstl,
                                        const __half* __restrict__ wh,
                                        const __half* __restrict__ wl,
                                        int tid)
{
    constexpr int VPA = ICA / 8;
    constexpr int PB  = (ICA + 8) * 2;
    const char* bh = (const char*)wh;
    const char* bl = (const char*)wl;
    for (int vi = tid; vi < 64 * VPA; vi += 256) {
        int row = vi / VPA, kv = vi % VPA;
        uint32_t d = row * PB + kv * 16;
        cp16(dsth + d, bh + vi * 16, true);
        if (LO) cp16(dstl + d, bl + vi * 16, true);
    }
}

// ---------------------------------------------------------------------------
// Implicit 3x3 conv via mma.sync; A halo resident, B double-buffered pipeline.
// CTA = 128 px (2 image rows) x 64 oc, 8 warps (4M x 2N), warp = 32px x 32oc.
// PROD=3: AhBh + AhBl + AlBh (conv0).  PROD=1: AhBh (pure fp16; convs 1-3).
// Output: fp16 hi activations, or fp32 (conv3).
// ---------------------------------------------------------------------------
template<int ICA, int PROD>
__global__ __launch_bounds__(256)
void conv_mma_kernel(const __half* __restrict__ in_hi,
                     const __half* __restrict__ in_lo,
                     const __half* __restrict__ wb_hi,
                     const __half* __restrict__ wb_lo,
                     const float* __restrict__ bias,
                     __half* __restrict__ out_hi,
                     float* __restrict__ out_f32,
                     int OC_total)
{
    constexpr int PITCH = ICA + 8;
    constexpr int PB    = PITCH * 2;
    constexpr int AROWS = 4 * 66;
    constexpr int ATILE = AROWS * PB;
    constexpr int BTILE = 64 * PB;
    constexpr int VPA   = ICA / 8;
    constexpr int KC    = ICA / 16;
    constexpr bool ALO  = (PROD == 3);
    constexpr bool BLO  = (PROD == 3);
    constexpr int BSTRIDE = BLO ? 2 : 1;    // BTILEs per buffer

    extern __shared__ char smem[];
    const uint32_t sAh = smem_u32(smem);
    const uint32_t sAl = sAh + ATILE;                       // valid only if ALO
    const uint32_t sB  = sAh + ATILE * (ALO ? 2 : 1);       // [buf][hi|lo]

    const int tid  = threadIdx.x;
    const int lane = tid & 31;
    const int warp = tid >> 5;
    const int warpN = warp & 1;             // 2 N tiles of 32 oc
    const int warpM = warp >> 1;            // 4 M tiles of 32 px

    const int pixbase = blockIdx.x * 128;
    const int b  = pixbase >> 12;
    const int y0 = (pixbase & 4095) >> 6;
    const int ocb = blockIdx.y;
    const bool active = (ocb * 64 + warpN * 32) < OC_total;
    const size_t wbase = (size_t)ocb * 9 * (64 * ICA);

    float acc[2][4][4];
    #pragma unroll
    for (int mt = 0; mt < 2; mt++)
        #pragma unroll
        for (int nt = 0; nt < 4; nt++)
            #pragma unroll
            for (int q = 0; q < 4; q++) acc[mt][nt][q] = 0.0f;

    // ---- prologue: A halo + B[0] (group0), B[1] (group1) ----
    for (int vi = tid; vi < AROWS * VPA; vi += 256) {
        int row = vi / VPA;
        int kv  = vi % VPA;
        int yy  = y0 + row / 66 - 1;
        int xx  = (row % 66) - 1;
        bool ok = (yy >= 0 && yy < Hh && xx >= 0 && xx < Ww);
        size_t src = ok ? (((size_t)((b << 12) + (yy << 6) + xx)) * ICA + kv * 8) : 0;
        uint32_t dst = row * PB + kv * 16;
        cp16(sAh + dst, in_hi + src, ok);
        if (ALO) cp16(sAl + dst, in_lo + src, ok);
    }
    stage_B<ICA, BLO>(sB, sB + BTILE, wb_hi + wbase, wb_lo + wbase, tid);
    CP_COMMIT();
    stage_B<ICA, BLO>(sB + BSTRIDE * BTILE, sB + (BSTRIDE + 1) * BTILE,
                      wb_hi + wbase + 64 * ICA, wb_lo + wbase + 64 * ICA, tid);
    CP_COMMIT();
    CP_WAIT1();
    __syncthreads();

    // per-lane ldmatrix base offsets
    const uint32_t a_base = (uint32_t)(((warpM >> 1) + 1) * 66
                          + (warpM & 1) * 32 + (lane & 15) + 1) * PB
                          + (uint32_t)(lane & 16);
    const uint32_t b_base = (uint32_t)(warpN * 32 + (lane & 7) + ((lane & 16) >> 1)) * PB
                          + (uint32_t)((lane & 8) << 1);

    for (int tap = 0; tap < 9; tap++) {
        const uint32_t bufh = sB + (uint32_t)(tap & 1) * (BSTRIDE * BTILE);
        const uint32_t bufl = bufh + BTILE;

        if (active) {
            const int dy = tap / 3 - 1, dx = tap % 3 - 1;
            const uint32_t tapoff = (uint32_t)((dy * 66 + dx) * PB);
            #pragma unroll
            for (int kc = 0; kc < KC; kc++) {
                const uint32_t k0b = kc * 32;
                uint32_t Ah[2][4], Al[2][4], Bh[2][4], Bl[2][4];
                #pragma unroll
                for (int mt = 0; mt < 2; mt++) {
                    uint32_t off = a_base + tapoff + k0b + (uint32_t)(mt * 16) * PB;
                    ldsm_x4(Ah[mt], sAh + off);
                    if (ALO) ldsm_x4(Al[mt], sAl + off);
                }
                #pragma unroll
                for (int p = 0; p < 2; p++) {
                    uint32_t off = b_base + k0b + (uint32_t)(p * 16) * PB;
                    ldsm_x4(Bh[p], bufh + off);
                    if (BLO) ldsm_x4(Bl[p], bufl + off);
                }
                #pragma unroll
                for (int mt = 0; mt < 2; mt++) {
                    #pragma unroll
                    for (int nt = 0; nt < 4; nt++) {
                        const int pr = nt >> 1, rr = (nt & 1) * 2;
                        mma16816(acc[mt][nt], Ah[mt], Bh[pr][rr], Bh[pr][rr + 1]);
                        if (PROD == 3) {
                            mma16816(acc[mt][nt], Ah[mt], Bl[pr][rr], Bl[pr][rr + 1]);
                            mma16816(acc[mt][nt], Al[mt], Bh[pr][rr], Bh[pr][rr + 1]);
                        }
                    }
                }
            }
        }
        __syncthreads();   // all warps done reading buf[tap&1]
        if (tap + 2 <= 8) {
            uint32_t nbh = sB + (uint32_t)(tap & 1) * (BSTRIDE * BTILE);
            stage_B<ICA, BLO>(nbh, nbh + BTILE,
                              wb_hi + wbase + (size_t)(tap + 2) * 64 * ICA,
                              wb_lo + wbase + (size_t)(tap + 2) * 64 * ICA, tid);
            CP_COMMIT();
            CP_WAIT1();    // B[tap+1] complete (only B[tap+2] may pend)
        } else {
            CP_WAIT0();
        }
        __syncthreads();
    }

    // --- epilogue ---
    if (!active) return;
    #pragma unroll
    for (int mt = 0; mt < 2; mt++) {
        #pragma unroll
        for (int nt = 0; nt < 4; nt++) {
            const int cl = warpN * 32 + nt * 8 + (lane & 3) * 2;   // local oc (even)
            const int oc = ocb * 64 + cl;                          // global oc
            if (oc >= OC_total) continue;
            const float b0 = bias[oc], b1 = bias[oc + 1];
            const int r0 = pixbase + (warpM >> 1) * 64 + (warpM & 1) * 32
                         + mt * 16 + (lane >> 2);
            #pragma unroll
            for (int h = 0; h < 2; h++) {
                const int pix = r0 + h * 8;
                float v0 = acc[mt][nt][2 * h]     + b0;
                float v1 = acc[mt][nt][2 * h + 1] + b1;
                if (out_f32) {
                    float2 fv = make_float2(v0, v1);
                    *(float2*)(out_f32 + (size_t)pix * OC4 + oc) = fv;
                } else {
                    v0 = eluf(v0);
                    v1 = eluf(v1);
                    __half h0 = __float2half_rn(v0);
                    __half h1 = __float2half_rn(v1);
                    uint32_t hw = (uint32_t)__half_as_ushort(h0) | ((uint32_t)__half_as_ushort(h1) << 16);
                    *(uint32_t*)(out_hi + (size_t)pix * 128 + oc) = hw;
                }
            }
        }
    }
}

// ---------------------------------------------------------------------------
// expm kernel, MATVEC form: y2 = sum_k A^k x2 / k!, 18 matvecs per pixel.
// ---------------------------------------------------------------------------
__global__ __launch_bounds__(256)
void expm_kernel(const float* __restrict__ o,
                 const float* __restrict__ scale, const float* __restrict__ shift_p,
                 const float* __restrict__ rescale, const float* __restrict__ reshift,
                 float* __restrict__ out)
{
    __shared__ float sT[16][20];
    __shared__ float sY[16][17];
    __shared__ float sTr[8];

    const int tid  = threadIdx.x;
    const int lane = tid & 31;
    const int warp = tid >> 5;
    const int half = lane >> 4;
    const int r    = lane & 15;
    const int pixB = warp * 2 + half;

    const int pix_base = blockIdx.x * 16;
    const int b  = pix_base >> 12;
    const int p  = pix_base & 4095;
    const int y  = p >> 6;
    const int x0 = p & 63;
    const int pix = pix_base + pixB;

    const float sc = scale[0], sp = shift_p[0], rs = rescale[0], rf = reshift[0];
    const float* op = o + (size_t)pix * OC4;

    float arow[16];
    #pragma unroll
    for (int j = 0; j < 16; j++) {
        float v = op[(j + 1) * 16 + r];
        arow[j] = rs * tanhf(sc * v + sp) + rf;
    }
    float tr = arow[r];

    const float x2v = g_x2t[(size_t)pix * 16 + r];
    sT[pixB][r] = x2v;
    float yacc = x2v;
    __syncwarp();

    #pragma unroll
    for (int k = 1; k <= 18; k++) {
        float s = 0.0f;
        #pragma unroll
        for (int j = 0; j < 16; j++) s += arow[j] * sT[pixB][j];
        s *= (1.0f / (float)k);
        __syncwarp();
        sT[pixB][r] = s;
        __syncwarp();
        yacc += s;
    }

    sY[pixB][r] = yacc + op[r];

    #pragma unroll
    for (int off = 16; off > 0; off >>= 1) tr += __shfl_down_sync(0xffffffffu, tr, off);
    if (lane == 0) sTr[warp] = tr;
    __syncthreads();
    if (tid == 0) {
        float s = 0.0f;
        #pragma unroll
        for (int w2 = 0; w2 < 8; w2++) s += sTr[w2];
        atomicAdd(out + (size_t)Bn * 32 * Hh * Ww + b, s);
    }

    const int c  = tid >> 4;
    const int p2 = tid & 15;
    out[((size_t)(b * 32 + 16 + c)) * (Hh * Ww) + y * Ww + x0 + p2] = sY[p2][c];
}

// ---------------------------------------------------------------------------
extern "C" void kernel_launch(void* const* d_in, const int* in_sizes, int n_in,
                              void* d_out, int out_size)
{
    const float* x       = (const float*)d_in[0];
    const float* scale   = (const float*)d_in[1];
    const float* shift_p = (const float*)d_in[2];
    const float* rescale = (const float*)d_in[3];
    const float* reshift = (const float*)d_in[4];
    const float* w0 = (const float*)d_in[5];
    const float* b0 = (const float*)d_in[6];
    const float* w1 = (const float*)d_in[7];
    const float* b1 = (const float*)d_in[8];
    const float* w2 = (const float*)d_in[9];
    const float* b2 = (const float*)d_in[10];
    const float* w3 = (const float*)d_in[11];
    const float* b3 = (const float*)d_in[12];
    float* out = (float*)d_out;

    __half *x1h, *x1l, *a0, *a1;
    __half *wb0h, *wb0l, *wb1h, *wb2h, *wb3h;
    float *x2t, *oB;
    cudaGetSymbolAddress((void**)&x1h, g_x1h);
    cudaGetSymbolAddress((void**)&x1l, g_x1l);
    cudaGetSymbolAddress((void**)&x2t, g_x2t);
    cudaGetSymbolAddress((void**)&a0,  g_a0);
    cudaGetSymbolAddress((void**)&a1,  g_a1);
    cudaGetSymbolAddress((void**)&oB,  g_o);
    cudaGetSymbolAddress((void**)&wb0h, g_wb0h);
    cudaGetSymbolAddress((void**)&wb0l, g_wb0l);
    cudaGetSymbolAddress((void**)&wb1h, g_wb1h);
    cudaGetSymbolAddress((void**)&wb2h, g_wb2h);
    cudaGetSymbolAddress((void**)&wb3h, g_wb3h);

    // SMEM: PROD=3 (conv0): A hi/lo + B 2x(hi,lo);  PROD=1: A hi + B 2x(hi)
    const int SMEM0_3 = 4 * 66 * (16 + 8) * 2 * 2  + 4 * 64 * (16 + 8) * 2;   //  37,632
    const int SMEM1_1 = 4 * 66 * (128 + 8) * 2     + 2 * 64 * (128 + 8) * 2;  // 106,624 -> 2 CTAs/SM
    cudaFuncSetAttribute(conv_mma_kernel<16, 3>,  cudaFuncAttributeMaxDynamicSharedMemorySize, SMEM0_3);
    cudaFuncSetAttribute(conv_mma_kernel<128, 1>, cudaFuncAttributeMaxDynamicSharedMemorySize, SMEM1_1);

    // 1) split / passthrough
    {
        int n = Bn * 32 * Hh * Ww;
        prep_kernel<<<(n + 255) / 256, 256>>>(x, out);
    }
    // 2) weight tiling (fp16, 64-oc tiles; lo only for conv0)
    {
        int n0 = 2 * 9 * 64 * 16;
        wprep_kernel<<<(n0 + 255) / 256, 256>>>(w0, wb0h, wb0l, HIDc, C1, n0);
        int n1 = 2 * 9 * 64 * 128;
        wprep_kernel<<<(n1 + 255) / 256, 256>>>(w1, wb1h, (__half*)nullptr, HIDc, HIDc, n1);
        wprep_kernel<<<(n1 + 255) / 256, 256>>>(w2, wb2h, (__half*)nullptr, HIDc, HIDc, n1);
        int n3 = 5 * 9 * 64 * 128;
        wprep_kernel<<<(n3 + 255) / 256, 256>>>(w3, wb3h, (__half*)nullptr, OC4, HIDc, n3);
    }
    // 3) convs: conv0 3-product (raw input), convs 1-3 pure fp16 1-product
    conv_mma_kernel<16, 3><<<dim3(NPIX / 128, 2), 256, SMEM0_3>>>(
        x1h, x1l, wb0h, wb0l, b0, a0, nullptr, HIDc);
    conv_mma_kernel<128, 1><<<dim3(NPIX / 128, 2), 256, SMEM1_1>>>(
        a0, a0, wb1h, wb1h, b1, a1, nullptr, HIDc);
    conv_mma_kernel<128, 1><<<dim3(NPIX / 128, 2), 256, SMEM1_1>>>(
        a1, a1, wb2h, wb2h, b2, a0, nullptr, HIDc);
    conv_mma_kernel<128, 1><<<dim3(NPIX / 128, 5), 256, SMEM1_1>>>(
        a0, a0, wb3h, wb3h, b3, nullptr, oB, OC4);
    // 4) expm (matvec Taylor) + assembly + log_det
    expm_kernel<<<NPIX / 16, 256>>>(oB, scale, shift_p, rescale, reshift, out);

    (void)in_sizes; (void)n_in; (void)out_size;
}

// round 10
// speedup vs baseline: 16.8426x; 1.0673x over previous
#include <cuda_runtime.h>
#include <cuda_fp16.h>
#include <math.h>
#include <stdint.h>

// Shapes (fixed)
#define Bn   16
#define Hh   64
#define Ww   64
#define C1   16
#define C2   16
#define HIDc 128
#define OC4  272          // C2*(C2+1)
#define NPIX (Bn*Hh*Ww)   // 65536

// ---------------------------------------------------------------------------
__device__ __forceinline__ uint32_t smem_u32(const void* p) {
    uint32_t a;
    asm("{ .reg .u64 t; cvta.to.shared.u64 t, %1; cvt.u32.u64 %0, t; }" : "=r"(a) : "l"(p));
    return a;
}

__device__ __forceinline__ void ldsm_x4(uint32_t (&r)[4], uint32_t addr) {
    asm volatile("ldmatrix.sync.aligned.m8n8.x4.shared.b16 {%0,%1,%2,%3}, [%4];"
        : "=r"(r[0]), "=r"(r[1]), "=r"(r[2]), "=r"(r[3]) : "r"(addr));
}

__device__ __forceinline__ void mma16816(float (&d)[4], const uint32_t (&a)[4],
                                         uint32_t b0, uint32_t b1) {
    asm volatile("mma.sync.aligned.m16n8k16.row.col.f32.f16.f16.f32 "
        "{%0,%1,%2,%3}, {%4,%5,%6,%7}, {%8,%9}, {%0,%1,%2,%3};"
        : "+f"(d[0]), "+f"(d[1]), "+f"(d[2]), "+f"(d[3])
        : "r"(a[0]), "r"(a[1]), "r"(a[2]), "r"(a[3]), "r"(b0), "r"(b1));
}

__device__ __forceinline__ void cp16(uint32_t dst, const void* src, bool pred) {
    asm volatile("cp.async.cg.shared.global [%0], [%1], 16, %2;"
        :: "r"(dst), "l"(src), "r"(pred ? 16u : 0u) : "memory");
}
#define CP_COMMIT() asm volatile("cp.async.commit_group;" ::: "memory")
#define CP_WAIT0()  asm volatile("cp.async.wait_group 0;" ::: "memory")
#define CP_WAIT1()  asm volatile("cp.async.wait_group 1;" ::: "memory")

__device__ __forceinline__ float eluf(float t) { return t > 0.0f ? t : expm1f(t); }

__device__ __forceinline__ float tanh_fast(float x) {
    float y;
    asm("tanh.approx.f32 %0, %1;" : "=f"(y) : "f"(x));
    return y;
}

// ---------------- scratch (device globals) ----------------
__device__ __align__(16) __half g_x1h[NPIX * C1];
__device__ __align__(16) float  g_x2t[NPIX * C2];
__device__ __align__(16) __half g_a0[NPIX * HIDc];
__device__ __align__(16) __half g_a1[NPIX * HIDc];
__device__ __align__(16) float  g_o [(size_t)NPIX * OC4];
// pre-tiled weights: [tile64][tap][64 oc][ICA] fp16
__device__ __align__(16) __half g_wb0[2 * 9 * 64 * 16];
__device__ __align__(16) __half g_wb1[2 * 9 * 64 * 128];
__device__ __align__(16) __half g_wb2[2 * 9 * 64 * 128];
__device__ __align__(16) __half g_wb3[5 * 9 * 64 * 128];

// ---------------------------------------------------------------------------
// prep: NCHW -> NHWC split (x1 as fp16, x2 fp32), passthrough, zero logdet
// ---------------------------------------------------------------------------
__global__ void prep_kernel(const float* __restrict__ x, float* __restrict__ out)
{
    int idx = blockIdx.x * blockDim.x + threadIdx.x;
    if (idx < Bn) out[(size_t)Bn * 32 * Hh * Ww + idx] = 0.0f;
    if (idx >= Bn * 32 * Hh * Ww) return;
    int b = idx >> 17;
    int c = (idx >> 12) & 31;
    int p = idx & 4095;
    float v = x[idx];
    int pix = (b << 12) + p;
    if (c < C1) {
        out[idx] = v;
        g_x1h[pix * C1 + c] = __float2half_rn(v);
    } else {
        g_x2t[pix * C2 + (c - C1)] = v;
    }
}

// ---------------------------------------------------------------------------
// wprep_all: tile ALL four weight tensors into fp16 64-oc tiles in one launch
// ---------------------------------------------------------------------------
#define WN0 (2 * 9 * 64 * 16)
#define WN1 (2 * 9 * 64 * 128)
#define WN3 (5 * 9 * 64 * 128)
__global__ void wprep_all(const float* __restrict__ w0, const float* __restrict__ w1,
                          const float* __restrict__ w2, const float* __restrict__ w3,
                          __half* __restrict__ d0, __half* __restrict__ d1,
                          __half* __restrict__ d2, __half* __restrict__ d3)
{
    int gi = blockIdx.x * blockDim.x + threadIdx.x;
    const float* w; __half* d; int OC, ICA, li;
    if (gi < WN0)                 { li = gi;                 w = w0; d = d0; OC = HIDc; ICA = C1;   }
    else if (gi < WN0 + WN1)      { li = gi - WN0;           w = w1; d = d1; OC = HIDc; ICA = HIDc; }
    else if (gi < WN0 + 2 * WN1)  { li = gi - WN0 - WN1;     w = w2; d = d2; OC = HIDc; ICA = HIDc; }
    else if (gi < WN0 + 2 * WN1 + WN3) { li = gi - WN0 - 2 * WN1; w = w3; d = d3; OC = OC4; ICA = HIDc; }
    else return;
    int k   = li % ICA;
    int row = (li / ICA) & 63;
    int tt  = li / (ICA * 64);
    int tap  = tt % 9;
    int tile = tt / 9;
    int oc = tile * 64 + row;
    float v = (oc < OC) ? w[((size_t)oc * ICA + k) * 9 + tap] : 0.0f;
    d[li] = __float2half_rn(v);
}

// ---------------------------------------------------------------------------
// B-tile stager: one tap (64 rows x ICA) into padded SMEM via cp.async
// ---------------------------------------------------------------------------
template<int ICA>
__device__ __forceinline__ void stage_B(uint32_t dst, const __half* __restrict__ wsrc, int tid)
{
    constexpr int VPA = ICA / 8;
    constexpr int PB  = (ICA + 8) * 2;
    const char* bsrc = (const char*)wsrc;
    for (int vi = tid; vi < 64 * VPA; vi += 256) {
        int row = vi / VPA, kv = vi % VPA;
        cp16(dst + row * PB + kv * 16, bsrc + vi * 16, true);
    }
}

// ---------------------------------------------------------------------------
// Implicit 3x3 conv via mma.sync (pure fp16); A halo resident, B double-buffered.
// CTA = 128 px (2 image rows) x 64 oc, 8 warps (4M x 2N), warp = 32px x 32oc.
// ---------------------------------------------------------------------------
template<int ICA>
__global__ __launch_bounds__(256)
void conv_mma_kernel(const __half* __restrict__ in,
                     const __half* __restrict__ wb,
                     const float* __restrict__ bias,
                     __half* __restrict__ out_h,
                     float* __restrict__ out_f32,
                     int OC_total)
{
    constexpr int PITCH = ICA + 8;
    constexpr int PB    = PITCH * 2;
    constexpr int AROWS = 4 * 66;
    constexpr int ATILE = AROWS * PB;
    constexpr int BTILE = 64 * PB;
    constexpr int VPA   = ICA / 8;
    constexpr int KC    = ICA / 16;

    extern __shared__ char smem[];
    const uint32_t sA = smem_u32(smem);
    const uint32_t sB = sA + ATILE;         // [2 bufs]

    const int tid  = threadIdx.x;
    const int lane = tid & 31;
    const int warp = tid >> 5;
    const int warpN = warp & 1;
    const int warpM = warp >> 1;

    const int pixbase = blockIdx.x * 128;
    const int b  = pixbase >> 12;
    const int y0 = (pixbase & 4095) >> 6;
    const int ocb = blockIdx.y;
    const bool active = (ocb * 64 + warpN * 32) < OC_total;
    const size_t wbase = (size_t)ocb * 9 * (64 * ICA);

    float acc[2][4][4];
    #pragma unroll
    for (int mt = 0; mt < 2; mt++)
        #pragma unroll
        for (int nt = 0; nt < 4; nt++)
            #pragma unroll
            for (int q = 0; q < 4; q++) acc[mt][nt][q] = 0.0f;

    // ---- prologue: A halo + B[0] (group0), B[1] (group1) ----
    for (int vi = tid; vi < AROWS * VPA; vi += 256) {
        int row = vi / VPA;
        int kv  = vi % VPA;
        int yy  = y0 + row / 66 - 1;
        int xx  = (row % 66) - 1;
        bool ok = (yy >= 0 && yy < Hh && xx >= 0 && xx < Ww);
        size_t src = ok ? (((size_t)((b << 12) + (yy << 6) + xx)) * ICA + kv * 8) : 0;
        cp16(sA + row * PB + kv * 16, in + src, ok);
    }
    stage_B<ICA>(sB, wb + wbase, tid);
    CP_COMMIT();
    stage_B<ICA>(sB + BTILE, wb + wbase + 64 * ICA, tid);
    CP_COMMIT();
    CP_WAIT1();
    __syncthreads();

    // per-lane ldmatrix base offsets
    const uint32_t a_base = (uint32_t)(((warpM >> 1) + 1) * 66
                          + (warpM & 1) * 32 + (lane & 15) + 1) * PB
                          + (uint32_t)(lane & 16);
    const uint32_t b_base = (uint32_t)(warpN * 32 + (lane & 7) + ((lane & 16) >> 1)) * PB
                          + (uint32_t)((lane & 8) << 1);

    for (int tap = 0; tap < 9; tap++) {
        const uint32_t buf = sB + (uint32_t)(tap & 1) * BTILE;

        if (active) {
            const int dy = tap / 3 - 1, dx = tap % 3 - 1;
            const uint32_t tapoff = (uint32_t)((dy * 66 + dx) * PB);
            #pragma unroll
            for (int kc = 0; kc < KC; kc++) {
                const uint32_t k0b = kc * 32;
                uint32_t A[2][4], B[2][4];
                #pragma unroll
                for (int mt = 0; mt < 2; mt++)
                    ldsm_x4(A[mt], sA + a_base + tapoff + k0b + (uint32_t)(mt * 16) * PB);
                #pragma unroll
                for (int p = 0; p < 2; p++)
                    ldsm_x4(B[p], buf + b_base + k0b + (uint32_t)(p * 16) * PB);
                #pragma unroll
                for (int mt = 0; mt < 2; mt++)
                    #pragma unroll
                    for (int nt = 0; nt < 4; nt++) {
                        const int pr = nt >> 1, rr = (nt & 1) * 2;
                        mma16816(acc[mt][nt], A[mt], B[pr][rr], B[pr][rr + 1]);
                    }
            }
        }
        __syncthreads();
        if (tap + 2 <= 8) {
            stage_B<ICA>(sB + (uint32_t)(tap & 1) * BTILE,
                         wb + wbase + (size_t)(tap + 2) * 64 * ICA, tid);
            CP_COMMIT();
            CP_WAIT1();
        } else {
            CP_WAIT0();
        }
        __syncthreads();
    }

    // --- epilogue ---
    if (!active) return;
    #pragma unroll
    for (int mt = 0; mt < 2; mt++) {
        #pragma unroll
        for (int nt = 0; nt < 4; nt++) {
            const int cl = warpN * 32 + nt * 8 + (lane & 3) * 2;
            const int oc = ocb * 64 + cl;
            if (oc >= OC_total) continue;
            const float b0 = bias[oc], b1 = bias[oc + 1];
            const int r0 = pixbase + (warpM >> 1) * 64 + (warpM & 1) * 32
                         + mt * 16 + (lane >> 2);
            #pragma unroll
            for (int h = 0; h < 2; h++) {
                const int pix = r0 + h * 8;
                float v0 = acc[mt][nt][2 * h]     + b0;
                float v1 = acc[mt][nt][2 * h + 1] + b1;
                if (out_f32) {
                    *(float2*)(out_f32 + (size_t)pix * OC4 + oc) = make_float2(v0, v1);
                } else {
                    v0 = eluf(v0);
                    v1 = eluf(v1);
                    __half h0 = __float2half_rn(v0);
                    __half h1 = __float2half_rn(v1);
                    uint32_t hw = (uint32_t)__half_as_ushort(h0) | ((uint32_t)__half_as_ushort(h1) << 16);
                    *(uint32_t*)(out_h + (size_t)pix * 128 + oc) = hw;
                }
            }
        }
    }
}

// ---------------------------------------------------------------------------
// expm kernel: y2 = sum_{k=0..12} A^k x2 / k!  (terms 13-18 < 2e-10, ||A||<=1)
// A via tanh.approx; trace via accurate tanhf. One syncwarp/iter (double buf).
// ---------------------------------------------------------------------------
__global__ __launch_bounds__(256)
void expm_kernel(const float* __restrict__ o,
                 const float* __restrict__ scale, const float* __restrict__ shift_p,
                 const float* __restrict__ rescale, const float* __restrict__ reshift,
                 float* __restrict__ out)
{
    __shared__ float sT[16][2][20];
    __shared__ float sY[16][17];
    __shared__ float sTr[8];

    const int tid  = threadIdx.x;
    const int lane = tid & 31;
    const int warp = tid >> 5;
    const int half = lane >> 4;
    const int r    = lane & 15;
    const int pixB = warp * 2 + half;

    const int pix_base = blockIdx.x * 16;
    const int b  = pix_base >> 12;
    const int p  = pix_base & 4095;
    const int y  = p >> 6;
    const int x0 = p & 63;
    const int pix = pix_base + pixB;

    const float sc = scale[0], sp = shift_p[0], rs = rescale[0], rf = reshift[0];
    const float* op = o + (size_t)pix * OC4;

    float arow[16];
    #pragma unroll
    for (int j = 0; j < 16; j++) {
        float v = op[(j + 1) * 16 + r];
        arow[j] = rs * tanh_fast(sc * v + sp) + rf;
    }
    // accurate trace (same math path as validated rounds)
    float tr = rs * tanhf(sc * op[(r + 1) * 16 + r] + sp) + rf;

    const float x2v = g_x2t[(size_t)pix * 16 + r];
    sT[pixB][0][r] = x2v;
    float yacc = x2v;
    __syncwarp();

    #pragma unroll
    for (int k = 1; k <= 12; k++) {
        const int prev = (k - 1) & 1, cur = k & 1;
        float s = 0.0f;
        #pragma unroll
        for (int j = 0; j < 16; j++) s = fmaf(arow[j], sT[pixB][prev][j], s);
        s *= (1.0f / (float)k);
        sT[pixB][cur][r] = s;
        yacc += s;
        __syncwarp();
    }

    sY[pixB][r] = yacc + op[r];

    #pragma unroll
    for (int off = 16; off > 0; off >>= 1) tr += __shfl_down_sync(0xffffffffu, tr, off);
    if (lane == 0) sTr[warp] = tr;
    __syncthreads();
    if (tid == 0) {
        float s = 0.0f;
        #pragma unroll
        for (int w2 = 0; w2 < 8; w2++) s += sTr[w2];
        atomicAdd(out + (size_t)Bn * 32 * Hh * Ww + b, s);
    }

    const int c  = tid >> 4;
    const int p2 = tid & 15;
    out[((size_t)(b * 32 + 16 + c)) * (Hh * Ww) + y * Ww + x0 + p2] = sY[p2][c];
}

// ---------------------------------------------------------------------------
extern "C" void kernel_launch(void* const* d_in, const int* in_sizes, int n_in,
                              void* d_out, int out_size)
{
    const float* x       = (const float*)d_in[0];
    const float* scale   = (const float*)d_in[1];
    const float* shift_p = (const float*)d_in[2];
    const float* rescale = (const float*)d_in[3];
    const float* reshift = (const float*)d_in[4];
    const float* w0 = (const float*)d_in[5];
    const float* b0 = (const float*)d_in[6];
    const float* w1 = (const float*)d_in[7];
    const float* b1 = (const float*)d_in[8];
    const float* w2 = (const float*)d_in[9];
    const float* b2 = (const float*)d_in[10];
    const float* w3 = (const float*)d_in[11];
    const float* b3 = (const float*)d_in[12];
    float* out = (float*)d_out;

    __half *x1h, *a0, *a1, *wb0, *wb1, *wb2, *wb3;
    float *x2t, *oB;
    cudaGetSymbolAddress((void**)&x1h, g_x1h);
    cudaGetSymbolAddress((void**)&x2t, g_x2t);
    cudaGetSymbolAddress((void**)&a0,  g_a0);
    cudaGetSymbolAddress((void**)&a1,  g_a1);
    cudaGetSymbolAddress((void**)&oB,  g_o);
    cudaGetSymbolAddress((void**)&wb0, g_wb0);
    cudaGetSymbolAddress((void**)&wb1, g_wb1);
    cudaGetSymbolAddress((void**)&wb2, g_wb2);
    cudaGetSymbolAddress((void**)&wb3, g_wb3);

    // SMEM: A halo (hi) + B double buffer (hi), pitch ICA+8
    const int SMEM0 = 4 * 66 * (16 + 8) * 2  + 2 * 64 * (16 + 8) * 2;    //  18,816
    const int SMEM1 = 4 * 66 * (128 + 8) * 2 + 2 * 64 * (128 + 8) * 2;   // 106,624
    cudaFuncSetAttribute(conv_mma_kernel<16>,  cudaFuncAttributeMaxDynamicSharedMemorySize, SMEM0);
    cudaFuncSetAttribute(conv_mma_kernel<128>, cudaFuncAttributeMaxDynamicSharedMemorySize, SMEM1);

    // 1) split / passthrough
    {
        int n = Bn * 32 * Hh * Ww;
        prep_kernel<<<(n + 255) / 256, 256>>>(x, out);
    }
    // 2) weight tiling (all four tensors, one launch)
    {
        int n = WN0 + 2 * WN1 + WN3;
        wprep_all<<<(n + 255) / 256, 256>>>(w0, w1, w2, w3, wb0, wb1, wb2, wb3);
    }
    // 3) convs, pure fp16 1-product
    conv_mma_kernel<16><<<dim3(NPIX / 128, 2), 256, SMEM0>>>(
        x1h, wb0, b0, a0, nullptr, HIDc);
    conv_mma_kernel<128><<<dim3(NPIX / 128, 2), 256, SMEM1>>>(
        a0, wb1, b1, a1, nullptr, HIDc);
    conv_mma_kernel<128><<<dim3(NPIX / 128, 2), 256, SMEM1>>>(
        a1, wb2, b2, a0, nullptr, HIDc);
    conv_mma_kernel<128><<<dim3(NPIX / 128, 5), 256, SMEM1>>>(
        a0, wb3, b3, nullptr, oB, OC4);
    // 4) expm (12-term matvec Taylor) + assembly + log_det
    expm_kernel<<<NPIX / 16, 256>>>(oB, scale, shift_p, rescale, reshift, out);

    (void)in_sizes; (void)n_in; (void)out_size;
}